// round 10
// baseline (speedup 1.0000x reference)
#include <cuda_runtime.h>
#include <cuda_bf16.h>
#include <cstdint>

#define N_NODES 1000000
#define D_IN    128
#define H1      64
#define D2C     256
#define GS      128
#define NG      4096
#define TILE_M  256
#define N_TILES ((N_NODES + TILE_M - 1) / TILE_M)   // 3907

__device__ float g_graph_states[NG * GS];
__device__ __align__(16) __nv_bfloat16 gW1h[H1 * D_IN];    // [n][k]
__device__ __align__(16) __nv_bfloat16 gW1l[H1 * D_IN];
__device__ __align__(16) __nv_bfloat16 gW2h[D2C * H1];     // [n][k]
__device__ __align__(16) __nv_bfloat16 gW2l[D2C * H1];

// ---------------- helpers ----------------
__device__ __forceinline__ uint32_t smem_u32(const void* p) {
    uint32_t a;
    asm("{ .reg .u64 t; cvta.to.shared.u64 t, %1; cvt.u32.u64 %0, t; }" : "=r"(a) : "l"(p));
    return a;
}
__device__ __forceinline__ void ldsm4(uint32_t* r, uint32_t addr) {
    asm volatile("ldmatrix.sync.aligned.m8n8.x4.shared.b16 {%0,%1,%2,%3}, [%4];"
                 : "=r"(r[0]), "=r"(r[1]), "=r"(r[2]), "=r"(r[3]) : "r"(addr));
}
__device__ __forceinline__ void hmma(float* d, const uint32_t* a, uint32_t b0, uint32_t b1) {
    asm volatile("mma.sync.aligned.m16n8k16.row.col.f32.bf16.bf16.f32 "
                 "{%0,%1,%2,%3}, {%4,%5,%6,%7}, {%8,%9}, {%0,%1,%2,%3};"
                 : "+f"(d[0]), "+f"(d[1]), "+f"(d[2]), "+f"(d[3])
                 : "r"(a[0]), "r"(a[1]), "r"(a[2]), "r"(a[3]), "r"(b0), "r"(b1));
}
__device__ __forceinline__ uint32_t cvt_hi(float f0, float f1) {
    uint32_t r;
    asm("cvt.rn.bf16x2.f32 %0, %1, %2;" : "=r"(r) : "f"(f1), "f"(f0));
    return r;
}
__device__ __forceinline__ uint32_t cvt_hilo(float f0, float f1, uint32_t& hi) {
    hi = cvt_hi(f0, f1);
    float h0 = __uint_as_float(hi << 16);
    float h1 = __uint_as_float(hi & 0xffff0000u);
    return cvt_hi(f0 - h0, f1 - h1);
}
__device__ __forceinline__ void red4(float* p, float x, float y, float z, float w) {
    asm volatile("red.global.add.v4.f32 [%0], {%1,%2,%3,%4};"
                 :: "l"(p), "f"(x), "f"(y), "f"(z), "f"(w) : "memory");
}
__device__ __forceinline__ float sigmul(float v, float g) {
    return __fdividef(v, 1.f + __expf(-g));
}

// ---------------- prep: W transpose + hi/lo split ----------------
__global__ void prep_kernel(const float* __restrict__ W1, const float* __restrict__ W2) {
    int i = blockIdx.x * blockDim.x + threadIdx.x;
    if (i < H1 * D_IN) {
        int n = i >> 7, k = i & 127;
        float w = W1[k * H1 + n];
        __nv_bfloat16 h = __float2bfloat16(w);
        gW1h[i] = h;
        gW1l[i] = __float2bfloat16(w - __bfloat162float(h));
    }
    if (i < D2C * H1) {
        int n = i >> 6, k = i & 63;
        float w = W2[k * D2C + n];
        __nv_bfloat16 h = __float2bfloat16(w);
        gW2h[i] = h;
        gW2l[i] = __float2bfloat16(w - __bfloat162float(h));
    }
}

// ---------------- SMEM layout (bytes) ----------------
#define OF_XH  0          // 256 rows x 256B (swizzled, 16 chunks)
#define OF_XL  65536
#define OF_W1H 131072     // 64 rows x 256B
#define OF_W1L 147456
#define OF_W2H 163840     // 256 rows x 128B (8 chunks)
#define OF_W2L 196608
#define OF_B1  229376     // 64 f32
#define OF_B2  229632     // 256 f32
#define OF_GI  230656     // 256 int
#define SMEM_TOTAL 231680

// ---------------- fused HMMA kernel: 256 threads, TILE_M=256 ----------------
__global__ __launch_bounds__(256, 1)
void mma_fused_kernel(const float* __restrict__ X, const int* __restrict__ gidx,
                      const float* __restrict__ b1, const float* __restrict__ b2,
                      int tile_begin, int tile_end)
{
    extern __shared__ char smem[];
    const uint32_t sb = smem_u32(smem);
    const int tid = threadIdx.x;
    const int L   = tid & 31;
    const int m0  = (tid >> 5) * 32;            // warp's 32 rows (8 warps x 32 = 256)
    float* b1s = (float*)(smem + OF_B1);
    float* b2s = (float*)(smem + OF_B2);
    int*   sGI = (int*)(smem + OF_GI);

    // ---- stage weights (swizzled for ldmatrix) + biases ----
    for (int i = tid; i < H1 * 16; i += 256) {            // W1: 64 rows x 16 chunks
        int n = i >> 4, c = i & 15;
        uint32_t off = n * 256 + ((c ^ (n & 7)) << 4);
        *(uint4*)(smem + OF_W1H + off) = *(const uint4*)(gW1h + n * D_IN + c * 8);
        *(uint4*)(smem + OF_W1L + off) = *(const uint4*)(gW1l + n * D_IN + c * 8);
    }
    for (int i = tid; i < D2C * 8; i += 256) {            // W2: 256 rows x 8 chunks
        int n = i >> 3, c = i & 7;
        uint32_t off = n * 128 + ((c ^ (n & 7)) << 4);
        *(uint4*)(smem + OF_W2H + off) = *(const uint4*)(gW2h + n * H1 + c * 8);
        *(uint4*)(smem + OF_W2L + off) = *(const uint4*)(gW2l + n * H1 + c * 8);
    }
    if (tid < 64) b1s[tid] = b1[tid];
    if (tid < 256) b2s[tid] = b2[tid];
    __syncthreads();

    for (int tile = tile_begin + blockIdx.x; tile < tile_end; tile += gridDim.x) {
        // ---- phase A: X row (1 per thread) -> hi/lo bf16 swizzled SMEM ----
        const int node = tile * TILE_M + tid;
        const bool valid = node < N_NODES;
        sGI[tid] = valid ? __ldg(&gidx[node]) : -1;
        const float4* xr = (const float4*)(X + (size_t)node * D_IN);
        #pragma unroll 4
        for (int c = 0; c < 16; ++c) {
            uint4 H = make_uint4(0, 0, 0, 0), Lo = make_uint4(0, 0, 0, 0);
            if (valid) {
                float4 a = __ldg(&xr[2 * c]), b = __ldg(&xr[2 * c + 1]);
                Lo.x = cvt_hilo(a.x, a.y, H.x);
                Lo.y = cvt_hilo(a.z, a.w, H.y);
                Lo.z = cvt_hilo(b.x, b.y, H.z);
                Lo.w = cvt_hilo(b.z, b.w, H.w);
            }
            uint32_t off = tid * 256 + ((c ^ (tid & 7)) << 4);
            *(uint4*)(smem + OF_XH + off) = H;
            *(uint4*)(smem + OF_XL + off) = Lo;
        }
        __syncthreads();

        // ---- layer 1: warp's [32,128] @ W1^T[128,64], 3 split products ----
        float acc[2][8][4];
        #pragma unroll
        for (int mt = 0; mt < 2; ++mt)
            #pragma unroll
            for (int nt = 0; nt < 8; ++nt)
                #pragma unroll
                for (int j = 0; j < 4; ++j) acc[mt][nt][j] = 0.f;

        #pragma unroll 1
        for (int ks = 0; ks < 8; ++ks) {
            const int cc = ks * 2 + (L >> 4);
            uint32_t ah[2][4], al[2][4], bw[4][4];
            #pragma unroll
            for (int mt = 0; mt < 2; ++mt) {
                int r = m0 + mt * 16 + (L & 15);
                uint32_t off = r * 256 + ((cc ^ (r & 7)) << 4);
                ldsm4(ah[mt], sb + OF_XH + off);
                ldsm4(al[mt], sb + OF_XL + off);
            }
            #pragma unroll
            for (int np = 0; np < 4; ++np) {
                int rn = np * 16 + (L & 15);
                ldsm4(bw[np], sb + OF_W1H + rn * 256 + ((cc ^ (rn & 7)) << 4));
            }
            #pragma unroll
            for (int mt = 0; mt < 2; ++mt)
                #pragma unroll
                for (int np = 0; np < 4; ++np) {
                    hmma(acc[mt][2 * np],     ah[mt], bw[np][0], bw[np][2]);
                    hmma(acc[mt][2 * np + 1], ah[mt], bw[np][1], bw[np][3]);
                    hmma(acc[mt][2 * np],     al[mt], bw[np][0], bw[np][2]);
                    hmma(acc[mt][2 * np + 1], al[mt], bw[np][1], bw[np][3]);
                }
            #pragma unroll
            for (int np = 0; np < 4; ++np) {
                int rn = np * 16 + (L & 15);
                ldsm4(bw[np], sb + OF_W1L + rn * 256 + ((cc ^ (rn & 7)) << 4));
            }
            #pragma unroll
            for (int mt = 0; mt < 2; ++mt)
                #pragma unroll
                for (int np = 0; np < 4; ++np) {
                    hmma(acc[mt][2 * np],     ah[mt], bw[np][0], bw[np][2]);
                    hmma(acc[mt][2 * np + 1], ah[mt], bw[np][1], bw[np][3]);
                }
        }

        // ---- epilogue 1: relu(acc+b1) -> layer-2 A fragments (registers) ----
        uint32_t a2h[2][4][4], a2l[2][4][4];
        #pragma unroll
        for (int mt = 0; mt < 2; ++mt)
            #pragma unroll
            for (int kt = 0; kt < 4; ++kt)
                #pragma unroll
                for (int hf = 0; hf < 2; ++hf) {
                    const int nt = 2 * kt + hf;
                    const float* d = acc[mt][nt];
                    const int c0 = nt * 8 + (L & 3) * 2;
                    float2 bb = *(float2*)(b1s + c0);
                    float h0 = fmaxf(d[0] + bb.x, 0.f), h1 = fmaxf(d[1] + bb.y, 0.f);
                    float h2 = fmaxf(d[2] + bb.x, 0.f), h3 = fmaxf(d[3] + bb.y, 0.f);
                    a2l[mt][kt][2 * hf]     = cvt_hilo(h0, h1, a2h[mt][kt][2 * hf]);
                    a2l[mt][kt][2 * hf + 1] = cvt_hilo(h2, h3, a2h[mt][kt][2 * hf + 1]);
                }

        // ---- layer 2 + gate + scatter, 4 chunks of (32 gate + 32 value) cols ----
        #pragma unroll 1
        for (int ch = 0; ch < 4; ++ch) {
            float aG[2][4][4], aV[2][4][4];
            #pragma unroll
            for (int mt = 0; mt < 2; ++mt)
                #pragma unroll
                for (int nt = 0; nt < 4; ++nt)
                    #pragma unroll
                    for (int j = 0; j < 4; ++j) { aG[mt][nt][j] = 0.f; aV[mt][nt][j] = 0.f; }

            #pragma unroll
            for (int ks = 0; ks < 4; ++ks) {
                const int cc = ks * 2 + (L >> 4);
                uint32_t bg[2][4], bv[2][4];
                #pragma unroll
                for (int np = 0; np < 2; ++np) {
                    int rg = 32 * ch + np * 16 + (L & 15);
                    int rv = 128 + 32 * ch + np * 16 + (L & 15);
                    ldsm4(bg[np], sb + OF_W2H + rg * 128 + ((cc ^ (rg & 7)) << 4));
                    ldsm4(bv[np], sb + OF_W2H + rv * 128 + ((cc ^ (rv & 7)) << 4));
                }
                #pragma unroll
                for (int mt = 0; mt < 2; ++mt)
                    #pragma unroll
                    for (int np = 0; np < 2; ++np) {
                        hmma(aG[mt][2 * np],     a2h[mt][ks], bg[np][0], bg[np][2]);
                        hmma(aG[mt][2 * np + 1], a2h[mt][ks], bg[np][1], bg[np][3]);
                        hmma(aV[mt][2 * np],     a2h[mt][ks], bv[np][0], bv[np][2]);
                        hmma(aV[mt][2 * np + 1], a2h[mt][ks], bv[np][1], bv[np][3]);
                        hmma(aG[mt][2 * np],     a2l[mt][ks], bg[np][0], bg[np][2]);
                        hmma(aG[mt][2 * np + 1], a2l[mt][ks], bg[np][1], bg[np][3]);
                        hmma(aV[mt][2 * np],     a2l[mt][ks], bv[np][0], bv[np][2]);
                        hmma(aV[mt][2 * np + 1], a2l[mt][ks], bv[np][1], bv[np][3]);
                    }
                #pragma unroll
                for (int np = 0; np < 2; ++np) {
                    int rg = 32 * ch + np * 16 + (L & 15);
                    int rv = 128 + 32 * ch + np * 16 + (L & 15);
                    ldsm4(bg[np], sb + OF_W2L + rg * 128 + ((cc ^ (rg & 7)) << 4));
                    ldsm4(bv[np], sb + OF_W2L + rv * 128 + ((cc ^ (rv & 7)) << 4));
                }
                #pragma unroll
                for (int mt = 0; mt < 2; ++mt)
                    #pragma unroll
                    for (int np = 0; np < 2; ++np) {
                        hmma(aG[mt][2 * np],     a2h[mt][ks], bg[np][0], bg[np][2]);
                        hmma(aG[mt][2 * np + 1], a2h[mt][ks], bg[np][1], bg[np][3]);
                        hmma(aV[mt][2 * np],     a2h[mt][ks], bv[np][0], bv[np][2]);
                        hmma(aV[mt][2 * np + 1], a2h[mt][ks], bv[np][1], bv[np][3]);
                    }
            }

            // ---- epilogue: gated = v*sigmoid(g); pair-exchange -> red.v4 ----
            // Thread pair (L, L^1) holds the same rows (r, r+8) with adjacent
            // col-pairs. Even lane keeps row r, odd lane keeps row r+8; one
            // shfl.bfly swap per nt turns 2x red.v2 into 1x red.v4 per lane.
            #pragma unroll
            for (int mt = 0; mt < 2; ++mt) {
                const int rKeep = m0 + mt * 16 + (L >> 2) + (L & 1) * 8;
                const int giK = sGI[rKeep];
                float* const gsK = g_graph_states + (size_t)(giK < 0 ? 0 : giK) * GS;
                #pragma unroll
                for (int nt = 0; nt < 4; ++nt) {
                    const int cg = 32 * ch + nt * 8 + (L & 3) * 2;
                    float2 bgc = *(float2*)(b2s + cg);
                    float2 bvc = *(float2*)(b2s + 128 + cg);
                    // row r (d0,d1), row r+8 (d2,d3)
                    float gr0 = sigmul(aV[mt][nt][0] + bvc.x, aG[mt][nt][0] + bgc.x);
                    float gr1 = sigmul(aV[mt][nt][1] + bvc.y, aG[mt][nt][1] + bgc.y);
                    float gs0 = sigmul(aV[mt][nt][2] + bvc.x, aG[mt][nt][2] + bgc.x);
                    float gs1 = sigmul(aV[mt][nt][3] + bvc.y, aG[mt][nt][3] + bgc.y);
                    // send the row we are NOT keeping; receive partner's kept-row part
                    const bool even = (L & 1) == 0;
                    float s0 = even ? gs0 : gr0;
                    float s1 = even ? gs1 : gr1;
                    float r0 = __shfl_xor_sync(0xffffffffu, s0, 1);
                    float r1 = __shfl_xor_sync(0xffffffffu, s1, 1);
                    float mine0 = even ? gr0 : gs0;
                    float mine1 = even ? gr1 : gs1;
                    // even lane holds lower col-pair of the 4-col group
                    float v0 = even ? mine0 : r0;
                    float v1 = even ? mine1 : r1;
                    float v2 = even ? r0 : mine0;
                    float v3 = even ? r1 : mine1;
                    const int cb = 32 * ch + nt * 8 + ((L & 3) >> 1) * 4;
                    if (giK >= 0) red4(gsK + cb, v0, v1, v2, v3);
                }
            }
        }
        __syncthreads();
    }
}

// ---------------- MLP2 + re-zero accumulator ----------------
__global__ __launch_bounds__(128) void mlp2_rezero_kernel(
    const float* __restrict__ W3, const float* __restrict__ b3,
    const float* __restrict__ W4, const float* __restrict__ b4,
    float* __restrict__ out)
{
    __shared__ float W3s[GS * 32];
    __shared__ float W4s[32 * 16];
    __shared__ float b3s[32];
    __shared__ float b4s[16];

    const int tid = threadIdx.x;
    for (int i = tid; i < (GS * 32) / 4; i += 128) ((float4*)W3s)[i] = ((const float4*)W3)[i];
    for (int i = tid; i < (32 * 16) / 4; i += 128) ((float4*)W4s)[i] = ((const float4*)W4)[i];
    if (tid < 32) b3s[tid] = b3[tid];
    if (tid < 16) b4s[tid] = b4[tid];
    __syncthreads();

    const int g = blockIdx.x * 128 + tid;

    float h3[32];
    #pragma unroll
    for (int j = 0; j < 32; ++j) h3[j] = b3s[j];

    float4* gr = (float4*)(g_graph_states + (size_t)g * GS);
    #pragma unroll 1
    for (int k4 = 0; k4 < GS / 4; ++k4) {
        const float4 gv = gr[k4];
        #pragma unroll
        for (int kk = 0; kk < 4; ++kk) {
            const float gk = (kk == 0) ? gv.x : (kk == 1) ? gv.y : (kk == 2) ? gv.z : gv.w;
            const float* w = &W3s[(k4 * 4 + kk) * 32];
            #pragma unroll
            for (int j = 0; j < 32; ++j) h3[j] += gk * w[j];
        }
    }
    #pragma unroll
    for (int k4 = 0; k4 < GS / 4; ++k4) gr[k4] = make_float4(0.f, 0.f, 0.f, 0.f);

    float o[16];
    #pragma unroll
    for (int j = 0; j < 16; ++j) o[j] = b4s[j];
    #pragma unroll
    for (int k = 0; k < 32; ++k) {
        const float hk = fmaxf(h3[k], 0.f);
        #pragma unroll
        for (int j = 0; j < 16; ++j) o[j] += hk * W4s[k * 16 + j];
    }

    float4* op = (float4*)(out + (size_t)g * 16);
    op[0] = make_float4(o[0],  o[1],  o[2],  o[3]);
    op[1] = make_float4(o[4],  o[5],  o[6],  o[7]);
    op[2] = make_float4(o[8],  o[9],  o[10], o[11]);
    op[3] = make_float4(o[12], o[13], o[14], o[15]);
}

extern "C" void kernel_launch(void* const* d_in, const int* in_sizes, int n_in,
                              void* d_out, int out_size)
{
    const float* X  = (const float*)d_in[0];
    const int*   gi = (const int*)  d_in[1];
    const float* W1 = (const float*)d_in[2];
    const float* b1 = (const float*)d_in[3];
    const float* W2 = (const float*)d_in[4];
    const float* b2 = (const float*)d_in[5];
    const float* W3 = (const float*)d_in[6];
    const float* b3 = (const float*)d_in[7];
    const float* W4 = (const float*)d_in[8];
    const float* b4 = (const float*)d_in[9];
    float* out = (float*)d_out;

    cudaFuncSetAttribute(mma_fused_kernel,
                         cudaFuncAttributeMaxDynamicSharedMemorySize, SMEM_TOTAL);

    prep_kernel<<<64, 256>>>(W1, W2);
    // g_graph_states: zero-initialized at load; re-zeroed by mlp2_rezero each call.
    mma_fused_kernel<<<148, 256, SMEM_TOTAL>>>(X, gi, b1, b2,    0, 1954);
    mma_fused_kernel<<<148, 256, SMEM_TOTAL>>>(X, gi, b1, b2, 1954, N_TILES);
    mlp2_rezero_kernel<<<NG / 128, 128>>>(W3, b3, W4, b4, out);
}

// round 12
// speedup vs baseline: 1.0588x; 1.0588x over previous
#include <cuda_runtime.h>
#include <cuda_bf16.h>
#include <cstdint>

#define N_NODES 1000000
#define D_IN    128
#define H1      64
#define D2C     256
#define GS      128
#define NG      4096
#define TILE_M  256
#define N_TILES ((N_NODES + TILE_M - 1) / TILE_M)   // 3907

__device__ float g_graph_states[NG * GS];
__device__ __align__(16) __nv_bfloat16 gW1h[H1 * D_IN];    // [n][k]
__device__ __align__(16) __nv_bfloat16 gW1l[H1 * D_IN];
__device__ __align__(16) __nv_bfloat16 gW2h[D2C * H1];     // [n][k]
__device__ __align__(16) __nv_bfloat16 gW2l[D2C * H1];

// ---------------- helpers ----------------
__device__ __forceinline__ uint32_t smem_u32(const void* p) {
    uint32_t a;
    asm("{ .reg .u64 t; cvta.to.shared.u64 t, %1; cvt.u32.u64 %0, t; }" : "=r"(a) : "l"(p));
    return a;
}
__device__ __forceinline__ void ldsm4(uint32_t* r, uint32_t addr) {
    asm volatile("ldmatrix.sync.aligned.m8n8.x4.shared.b16 {%0,%1,%2,%3}, [%4];"
                 : "=r"(r[0]), "=r"(r[1]), "=r"(r[2]), "=r"(r[3]) : "r"(addr));
}
__device__ __forceinline__ void hmma(float* d, const uint32_t* a, uint32_t b0, uint32_t b1) {
    asm volatile("mma.sync.aligned.m16n8k16.row.col.f32.bf16.bf16.f32 "
                 "{%0,%1,%2,%3}, {%4,%5,%6,%7}, {%8,%9}, {%0,%1,%2,%3};"
                 : "+f"(d[0]), "+f"(d[1]), "+f"(d[2]), "+f"(d[3])
                 : "r"(a[0]), "r"(a[1]), "r"(a[2]), "r"(a[3]), "r"(b0), "r"(b1));
}
__device__ __forceinline__ uint32_t cvt_hi(float f0, float f1) {
    uint32_t r;
    asm("cvt.rn.bf16x2.f32 %0, %1, %2;" : "=r"(r) : "f"(f1), "f"(f0));
    return r;
}
__device__ __forceinline__ uint32_t cvt_hilo(float f0, float f1, uint32_t& hi) {
    hi = cvt_hi(f0, f1);
    float h0 = __uint_as_float(hi << 16);
    float h1 = __uint_as_float(hi & 0xffff0000u);
    return cvt_hi(f0 - h0, f1 - h1);
}
__device__ __forceinline__ void red4(float* p, float x, float y, float z, float w) {
    asm volatile("red.global.add.v4.f32 [%0], {%1,%2,%3,%4};"
                 :: "l"(p), "f"(x), "f"(y), "f"(z), "f"(w) : "memory");
}
__device__ __forceinline__ float sigmul(float v, float g) {
    return __fdividef(v, 1.f + __expf(-g));
}

// ---------------- prep: W transpose + hi/lo split ----------------
__global__ void prep_kernel(const float* __restrict__ W1, const float* __restrict__ W2) {
    int i = blockIdx.x * blockDim.x + threadIdx.x;
    if (i < H1 * D_IN) {
        int n = i >> 7, k = i & 127;
        float w = W1[k * H1 + n];
        __nv_bfloat16 h = __float2bfloat16(w);
        gW1h[i] = h;
        gW1l[i] = __float2bfloat16(w - __bfloat162float(h));
    }
    if (i < D2C * H1) {
        int n = i >> 6, k = i & 63;
        float w = W2[k * D2C + n];
        __nv_bfloat16 h = __float2bfloat16(w);
        gW2h[i] = h;
        gW2l[i] = __float2bfloat16(w - __bfloat162float(h));
    }
}

// ---------------- SMEM layout (bytes) ----------------
#define OF_XH  0          // 256 rows x 256B (swizzled, 16 chunks)
#define OF_XL  65536
#define OF_W1H 131072     // 64 rows x 256B
#define OF_W1L 147456
#define OF_W2H 163840     // 256 rows x 128B (8 chunks)
#define OF_W2L 196608
#define OF_B1  229376     // 64 f32
#define OF_B2  229632     // 256 f32
#define OF_GI  230656     // 256 int
#define SMEM_TOTAL 231680

// ---------------- fused HMMA kernel: 512 threads (16 warps), TILE_M=256 ----------------
__global__ __launch_bounds__(512, 1)
void mma_fused_kernel(const float* __restrict__ X, const int* __restrict__ gidx,
                      const float* __restrict__ b1, const float* __restrict__ b2,
                      int tile_begin, int tile_end)
{
    extern __shared__ char smem[];
    const uint32_t sb = smem_u32(smem);
    const int tid = threadIdx.x;
    const int L   = tid & 31;
    const int m0  = (tid >> 5) * 16;            // warp's 16 rows (16 warps x 16 = 256)
    float* b1s = (float*)(smem + OF_B1);
    float* b2s = (float*)(smem + OF_B2);
    int*   sGI = (int*)(smem + OF_GI);

    // ---- stage weights (swizzled for ldmatrix) + biases ----
    for (int i = tid; i < H1 * 16; i += 512) {            // W1: 64 rows x 16 chunks
        int n = i >> 4, c = i & 15;
        uint32_t off = n * 256 + ((c ^ (n & 7)) << 4);
        *(uint4*)(smem + OF_W1H + off) = *(const uint4*)(gW1h + n * D_IN + c * 8);
        *(uint4*)(smem + OF_W1L + off) = *(const uint4*)(gW1l + n * D_IN + c * 8);
    }
    for (int i = tid; i < D2C * 8; i += 512) {            // W2: 256 rows x 8 chunks
        int n = i >> 3, c = i & 7;
        uint32_t off = n * 128 + ((c ^ (n & 7)) << 4);
        *(uint4*)(smem + OF_W2H + off) = *(const uint4*)(gW2h + n * H1 + c * 8);
        *(uint4*)(smem + OF_W2L + off) = *(const uint4*)(gW2l + n * H1 + c * 8);
    }
    if (tid < 64) b1s[tid] = b1[tid];
    if (tid >= 64 && tid < 320) b2s[tid - 64] = b2[tid - 64];
    __syncthreads();

    for (int tile = tile_begin + blockIdx.x; tile < tile_end; tile += gridDim.x) {
        // ---- phase A: 2 threads per X row (8 chunks each) -> hi/lo bf16 SMEM ----
        const int row  = tid >> 1;
        const int half = tid & 1;
        const int node = tile * TILE_M + row;
        const bool valid = node < N_NODES;
        if (half == 0) sGI[row] = valid ? __ldg(&gidx[node]) : -1;
        const float4* xr = (const float4*)(X + (size_t)node * D_IN);
        #pragma unroll 4
        for (int cc8 = 0; cc8 < 8; ++cc8) {
            const int c = half * 8 + cc8;
            uint4 H = make_uint4(0, 0, 0, 0), Lo = make_uint4(0, 0, 0, 0);
            if (valid) {
                float4 a = __ldg(&xr[2 * c]), b = __ldg(&xr[2 * c + 1]);
                Lo.x = cvt_hilo(a.x, a.y, H.x);
                Lo.y = cvt_hilo(a.z, a.w, H.y);
                Lo.z = cvt_hilo(b.x, b.y, H.z);
                Lo.w = cvt_hilo(b.z, b.w, H.w);
            }
            uint32_t off = row * 256 + ((c ^ (row & 7)) << 4);
            *(uint4*)(smem + OF_XH + off) = H;
            *(uint4*)(smem + OF_XL + off) = Lo;
        }
        __syncthreads();

        // ---- layer 1: warp's [16,128] @ W1^T[128,64], 3 split products ----
        float acc[8][4];
        #pragma unroll
        for (int nt = 0; nt < 8; ++nt)
            #pragma unroll
            for (int j = 0; j < 4; ++j) acc[nt][j] = 0.f;

        #pragma unroll 1
        for (int ks = 0; ks < 8; ++ks) {
            const int cc = ks * 2 + (L >> 4);
            uint32_t ah[4], al[4], bw[4][4];
            {
                int r = m0 + (L & 15);
                uint32_t off = r * 256 + ((cc ^ (r & 7)) << 4);
                ldsm4(ah, sb + OF_XH + off);
                ldsm4(al, sb + OF_XL + off);
            }
            #pragma unroll
            for (int np = 0; np < 4; ++np) {
                int rn = np * 16 + (L & 15);
                ldsm4(bw[np], sb + OF_W1H + rn * 256 + ((cc ^ (rn & 7)) << 4));
            }
            #pragma unroll
            for (int np = 0; np < 4; ++np) {
                hmma(acc[2 * np],     ah, bw[np][0], bw[np][2]);
                hmma(acc[2 * np + 1], ah, bw[np][1], bw[np][3]);
                hmma(acc[2 * np],     al, bw[np][0], bw[np][2]);
                hmma(acc[2 * np + 1], al, bw[np][1], bw[np][3]);
            }
            #pragma unroll
            for (int np = 0; np < 4; ++np) {
                int rn = np * 16 + (L & 15);
                ldsm4(bw[np], sb + OF_W1L + rn * 256 + ((cc ^ (rn & 7)) << 4));
            }
            #pragma unroll
            for (int np = 0; np < 4; ++np) {
                hmma(acc[2 * np],     ah, bw[np][0], bw[np][2]);
                hmma(acc[2 * np + 1], ah, bw[np][1], bw[np][3]);
            }
        }

        // ---- epilogue 1: relu(acc+b1) -> layer-2 A fragments (registers) ----
        uint32_t a2h[4][4], a2l[4][4];
        #pragma unroll
        for (int kt = 0; kt < 4; ++kt)
            #pragma unroll
            for (int hf = 0; hf < 2; ++hf) {
                const int nt = 2 * kt + hf;
                const float* d = acc[nt];
                const int c0 = nt * 8 + (L & 3) * 2;
                float2 bb = *(float2*)(b1s + c0);
                float h0 = fmaxf(d[0] + bb.x, 0.f), h1 = fmaxf(d[1] + bb.y, 0.f);
                float h2 = fmaxf(d[2] + bb.x, 0.f), h3 = fmaxf(d[3] + bb.y, 0.f);
                a2l[kt][2 * hf]     = cvt_hilo(h0, h1, a2h[kt][2 * hf]);
                a2l[kt][2 * hf + 1] = cvt_hilo(h2, h3, a2h[kt][2 * hf + 1]);
            }

        // ---- layer 2 + gate + scatter, 4 chunks of (32 gate + 32 value) cols ----
        #pragma unroll 1
        for (int ch = 0; ch < 4; ++ch) {
            float aG[4][4], aV[4][4];
            #pragma unroll
            for (int nt = 0; nt < 4; ++nt)
                #pragma unroll
                for (int j = 0; j < 4; ++j) { aG[nt][j] = 0.f; aV[nt][j] = 0.f; }

            #pragma unroll
            for (int ks = 0; ks < 4; ++ks) {
                const int cc = ks * 2 + (L >> 4);
                uint32_t bg[2][4], bv[2][4];
                #pragma unroll
                for (int np = 0; np < 2; ++np) {
                    int rg = 32 * ch + np * 16 + (L & 15);
                    int rv = 128 + 32 * ch + np * 16 + (L & 15);
                    ldsm4(bg[np], sb + OF_W2H + rg * 128 + ((cc ^ (rg & 7)) << 4));
                    ldsm4(bv[np], sb + OF_W2H + rv * 128 + ((cc ^ (rv & 7)) << 4));
                }
                #pragma unroll
                for (int np = 0; np < 2; ++np) {
                    hmma(aG[2 * np],     a2h[ks], bg[np][0], bg[np][2]);
                    hmma(aG[2 * np + 1], a2h[ks], bg[np][1], bg[np][3]);
                    hmma(aV[2 * np],     a2h[ks], bv[np][0], bv[np][2]);
                    hmma(aV[2 * np + 1], a2h[ks], bv[np][1], bv[np][3]);
                    hmma(aG[2 * np],     a2l[ks], bg[np][0], bg[np][2]);
                    hmma(aG[2 * np + 1], a2l[ks], bg[np][1], bg[np][3]);
                    hmma(aV[2 * np],     a2l[ks], bv[np][0], bv[np][2]);
                    hmma(aV[2 * np + 1], a2l[ks], bv[np][1], bv[np][3]);
                }
                #pragma unroll
                for (int np = 0; np < 2; ++np) {
                    int rg = 32 * ch + np * 16 + (L & 15);
                    int rv = 128 + 32 * ch + np * 16 + (L & 15);
                    ldsm4(bg[np], sb + OF_W2L + rg * 128 + ((cc ^ (rg & 7)) << 4));
                    ldsm4(bv[np], sb + OF_W2L + rv * 128 + ((cc ^ (rv & 7)) << 4));
                }
                #pragma unroll
                for (int np = 0; np < 2; ++np) {
                    hmma(aG[2 * np],     a2h[ks], bg[np][0], bg[np][2]);
                    hmma(aG[2 * np + 1], a2h[ks], bg[np][1], bg[np][3]);
                    hmma(aV[2 * np],     a2h[ks], bv[np][0], bv[np][2]);
                    hmma(aV[2 * np + 1], a2h[ks], bv[np][1], bv[np][3]);
                }
            }

            // ---- epilogue: gated = v*sigmoid(g); pair-exchange -> red.v4 ----
            const int rKeep = m0 + (L >> 2) + (L & 1) * 8;
            const int giK = sGI[rKeep];
            float* const gsK = g_graph_states + (size_t)(giK < 0 ? 0 : giK) * GS;
            #pragma unroll
            for (int nt = 0; nt < 4; ++nt) {
                const int cg = 32 * ch + nt * 8 + (L & 3) * 2;
                float2 bgc = *(float2*)(b2s + cg);
                float2 bvc = *(float2*)(b2s + 128 + cg);
                float gr0 = sigmul(aV[nt][0] + bvc.x, aG[nt][0] + bgc.x);
                float gr1 = sigmul(aV[nt][1] + bvc.y, aG[nt][1] + bgc.y);
                float gs0 = sigmul(aV[nt][2] + bvc.x, aG[nt][2] + bgc.x);
                float gs1 = sigmul(aV[nt][3] + bvc.y, aG[nt][3] + bgc.y);
                const bool even = (L & 1) == 0;
                float s0 = even ? gs0 : gr0;
                float s1 = even ? gs1 : gr1;
                float r0 = __shfl_xor_sync(0xffffffffu, s0, 1);
                float r1 = __shfl_xor_sync(0xffffffffu, s1, 1);
                float mine0 = even ? gr0 : gs0;
                float mine1 = even ? gr1 : gs1;
                float v0 = even ? mine0 : r0;
                float v1 = even ? mine1 : r1;
                float v2 = even ? r0 : mine0;
                float v3 = even ? r1 : mine1;
                const int cb = 32 * ch + nt * 8 + ((L & 3) >> 1) * 4;
                if (giK >= 0) red4(gsK + cb, v0, v1, v2, v3);
            }
        }
        __syncthreads();
    }
}

// ---------------- MLP2 + re-zero accumulator ----------------
__global__ __launch_bounds__(128) void mlp2_rezero_kernel(
    const float* __restrict__ W3, const float* __restrict__ b3,
    const float* __restrict__ W4, const float* __restrict__ b4,
    float* __restrict__ out)
{
    __shared__ float W3s[GS * 32];
    __shared__ float W4s[32 * 16];
    __shared__ float b3s[32];
    __shared__ float b4s[16];

    const int tid = threadIdx.x;
    for (int i = tid; i < (GS * 32) / 4; i += 128) ((float4*)W3s)[i] = ((const float4*)W3)[i];
    for (int i = tid; i < (32 * 16) / 4; i += 128) ((float4*)W4s)[i] = ((const float4*)W4)[i];
    if (tid < 32) b3s[tid] = b3[tid];
    if (tid < 16) b4s[tid] = b4[tid];
    __syncthreads();

    const int g = blockIdx.x * 128 + tid;

    float h3[32];
    #pragma unroll
    for (int j = 0; j < 32; ++j) h3[j] = b3s[j];

    float4* gr = (float4*)(g_graph_states + (size_t)g * GS);
    #pragma unroll 1
    for (int k4 = 0; k4 < GS / 4; ++k4) {
        const float4 gv = gr[k4];
        #pragma unroll
        for (int kk = 0; kk < 4; ++kk) {
            const float gk = (kk == 0) ? gv.x : (kk == 1) ? gv.y : (kk == 2) ? gv.z : gv.w;
            const float* w = &W3s[(k4 * 4 + kk) * 32];
            #pragma unroll
            for (int j = 0; j < 32; ++j) h3[j] += gk * w[j];
        }
    }
    #pragma unroll
    for (int k4 = 0; k4 < GS / 4; ++k4) gr[k4] = make_float4(0.f, 0.f, 0.f, 0.f);

    float o[16];
    #pragma unroll
    for (int j = 0; j < 16; ++j) o[j] = b4s[j];
    #pragma unroll
    for (int k = 0; k < 32; ++k) {
        const float hk = fmaxf(h3[k], 0.f);
        #pragma unroll
        for (int j = 0; j < 16; ++j) o[j] += hk * W4s[k * 16 + j];
    }

    float4* op = (float4*)(out + (size_t)g * 16);
    op[0] = make_float4(o[0],  o[1],  o[2],  o[3]);
    op[1] = make_float4(o[4],  o[5],  o[6],  o[7]);
    op[2] = make_float4(o[8],  o[9],  o[10], o[11]);
    op[3] = make_float4(o[12], o[13], o[14], o[15]);
}

extern "C" void kernel_launch(void* const* d_in, const int* in_sizes, int n_in,
                              void* d_out, int out_size)
{
    const float* X  = (const float*)d_in[0];
    const int*   gi = (const int*)  d_in[1];
    const float* W1 = (const float*)d_in[2];
    const float* b1 = (const float*)d_in[3];
    const float* W2 = (const float*)d_in[4];
    const float* b2 = (const float*)d_in[5];
    const float* W3 = (const float*)d_in[6];
    const float* b3 = (const float*)d_in[7];
    const float* W4 = (const float*)d_in[8];
    const float* b4 = (const float*)d_in[9];
    float* out = (float*)d_out;

    cudaFuncSetAttribute(mma_fused_kernel,
                         cudaFuncAttributeMaxDynamicSharedMemorySize, SMEM_TOTAL);

    prep_kernel<<<64, 256>>>(W1, W2);
    // g_graph_states: zero-initialized at load; re-zeroed by mlp2_rezero each call.
    mma_fused_kernel<<<148, 512, SMEM_TOTAL>>>(X, gi, b1, b2,    0, 1954);
    mma_fused_kernel<<<148, 512, SMEM_TOTAL>>>(X, gi, b1, b2, 1954, N_TILES);
    mlp2_rezero_kernel<<<NG / 128, 128>>>(W3, b3, W4, b4, out);
}

// round 13
// speedup vs baseline: 1.3912x; 1.3140x over previous
#include <cuda_runtime.h>
#include <cuda_fp16.h>
#include <cstdint>

#define N_NODES 1000000
#define D_IN    128
#define H1      64
#define D2C     256
#define GS      128
#define NG      4096
#define TILE_M  256
#define N_TILES ((N_NODES + TILE_M - 1) / TILE_M)   // 3907

__device__ float g_graph_states[NG * GS];
__device__ __align__(16) __half gW1[H1 * D_IN];    // [n][k] = fp16(W1[k][n])
__device__ __align__(16) __half gW2[D2C * H1];     // [n][k] = fp16(W2[k][n])

// ---------------- helpers ----------------
__device__ __forceinline__ uint32_t smem_u32(const void* p) {
    uint32_t a;
    asm("{ .reg .u64 t; cvta.to.shared.u64 t, %1; cvt.u32.u64 %0, t; }" : "=r"(a) : "l"(p));
    return a;
}
__device__ __forceinline__ void ldsm4(uint32_t* r, uint32_t addr) {
    asm volatile("ldmatrix.sync.aligned.m8n8.x4.shared.b16 {%0,%1,%2,%3}, [%4];"
                 : "=r"(r[0]), "=r"(r[1]), "=r"(r[2]), "=r"(r[3]) : "r"(addr));
}
__device__ __forceinline__ void hmma(float* d, const uint32_t* a, uint32_t b0, uint32_t b1) {
    asm volatile("mma.sync.aligned.m16n8k16.row.col.f32.f16.f16.f32 "
                 "{%0,%1,%2,%3}, {%4,%5,%6,%7}, {%8,%9}, {%0,%1,%2,%3};"
                 : "+f"(d[0]), "+f"(d[1]), "+f"(d[2]), "+f"(d[3])
                 : "r"(a[0]), "r"(a[1]), "r"(a[2]), "r"(a[3]), "r"(b0), "r"(b1));
}
// pack (f0 low, f1 high) into fp16x2 hi-part; return fp16x2 of the residuals
__device__ __forceinline__ uint32_t cvt16_hilo(float f0, float f1, uint32_t& hi) {
    __half2 h = __floats2half2_rn(f0, f1);
    hi = *(uint32_t*)&h;
    float r0 = f0 - __low2float(h);
    float r1 = f1 - __high2float(h);
    __half2 l = __floats2half2_rn(r0, r1);
    return *(uint32_t*)&l;
}
__device__ __forceinline__ void red4(float* p, float x, float y, float z, float w) {
    asm volatile("red.global.add.v4.f32 [%0], {%1,%2,%3,%4};"
                 :: "l"(p), "f"(x), "f"(y), "f"(z), "f"(w) : "memory");
}
// v * sigmoid(g) via single-MUFU tanh
__device__ __forceinline__ float sigmul(float v, float g) {
    float t;
    asm("tanh.approx.f32 %0, %1;" : "=f"(t) : "f"(g * 0.5f));
    return v * (0.5f + 0.5f * t);
}

// ---------------- prep: W transpose + fp16 ----------------
__global__ void prep_kernel(const float* __restrict__ W1, const float* __restrict__ W2) {
    int i = blockIdx.x * blockDim.x + threadIdx.x;
    if (i < H1 * D_IN) {
        int n = i >> 7, k = i & 127;
        gW1[i] = __float2half_rn(W1[k * H1 + n]);
    }
    if (i < D2C * H1) {
        int n = i >> 6, k = i & 63;
        gW2[i] = __float2half_rn(W2[k * D2C + n]);
    }
}

// ---------------- SMEM layout (bytes) ----------------
#define OF_XH  0          // 256 rows x 256B (swizzled, 16 chunks)
#define OF_XL  65536
#define OF_W1  131072     // 64 rows x 256B
#define OF_W2  147456     // 256 rows x 128B (8 chunks)
#define OF_B1  180224     // 64 f32
#define OF_B2  180480     // 256 f32
#define OF_GI  181504     // 256 int
#define SMEM_TOTAL 182528

// ---------------- fused HMMA kernel: 512 threads (16 warps), TILE_M=256 ----------------
__global__ __launch_bounds__(512, 1)
void mma_fused_kernel(const float* __restrict__ X, const int* __restrict__ gidx,
                      const float* __restrict__ b1, const float* __restrict__ b2,
                      int tile_begin, int tile_end)
{
    extern __shared__ char smem[];
    const uint32_t sb = smem_u32(smem);
    const int tid = threadIdx.x;
    const int L   = tid & 31;
    const int m0  = (tid >> 5) * 16;            // warp's 16 rows (16 warps x 16 = 256)
    float* b1s = (float*)(smem + OF_B1);
    float* b2s = (float*)(smem + OF_B2);
    int*   sGI = (int*)(smem + OF_GI);

    // ---- stage weights (swizzled for ldmatrix) + biases ----
    for (int i = tid; i < H1 * 16; i += 512) {            // W1: 64 rows x 16 chunks
        int n = i >> 4, c = i & 15;
        uint32_t off = n * 256 + ((c ^ (n & 7)) << 4);
        *(uint4*)(smem + OF_W1 + off) = *(const uint4*)(gW1 + n * D_IN + c * 8);
    }
    for (int i = tid; i < D2C * 8; i += 512) {            // W2: 256 rows x 8 chunks
        int n = i >> 3, c = i & 7;
        uint32_t off = n * 128 + ((c ^ (n & 7)) << 4);
        *(uint4*)(smem + OF_W2 + off) = *(const uint4*)(gW2 + n * H1 + c * 8);
    }
    if (tid < 64) b1s[tid] = b1[tid];
    if (tid >= 64 && tid < 320) b2s[tid - 64] = b2[tid - 64];
    __syncthreads();

    for (int tile = tile_begin + blockIdx.x; tile < tile_end; tile += gridDim.x) {
        // ---- phase A: 2 threads per X row (8 chunks each) -> fp16 hi/lo SMEM ----
        const int row  = tid >> 1;
        const int half = tid & 1;
        const int node = tile * TILE_M + row;
        const bool valid = node < N_NODES;
        if (half == 0) sGI[row] = valid ? __ldg(&gidx[node]) : -1;
        const float4* xr = (const float4*)(X + (size_t)node * D_IN);
        #pragma unroll 4
        for (int cc8 = 0; cc8 < 8; ++cc8) {
            const int c = half * 8 + cc8;
            uint4 H = make_uint4(0, 0, 0, 0), Lo = make_uint4(0, 0, 0, 0);
            if (valid) {
                float4 a = __ldg(&xr[2 * c]), b = __ldg(&xr[2 * c + 1]);
                Lo.x = cvt16_hilo(a.x, a.y, H.x);
                Lo.y = cvt16_hilo(a.z, a.w, H.y);
                Lo.z = cvt16_hilo(b.x, b.y, H.z);
                Lo.w = cvt16_hilo(b.z, b.w, H.w);
            }
            uint32_t off = row * 256 + ((c ^ (row & 7)) << 4);
            *(uint4*)(smem + OF_XH + off) = H;
            *(uint4*)(smem + OF_XL + off) = Lo;
        }
        __syncthreads();

        // ---- layer 1: warp's [16,128] @ W1^T[128,64], 2 split products ----
        float acc[8][4];
        #pragma unroll
        for (int nt = 0; nt < 8; ++nt)
            #pragma unroll
            for (int j = 0; j < 4; ++j) acc[nt][j] = 0.f;

        #pragma unroll 1
        for (int ks = 0; ks < 8; ++ks) {
            const int cc = ks * 2 + (L >> 4);
            uint32_t ah[4], al[4], bw[4][4];
            {
                int r = m0 + (L & 15);
                uint32_t off = r * 256 + ((cc ^ (r & 7)) << 4);
                ldsm4(ah, sb + OF_XH + off);
                ldsm4(al, sb + OF_XL + off);
            }
            #pragma unroll
            for (int np = 0; np < 4; ++np) {
                int rn = np * 16 + (L & 15);
                ldsm4(bw[np], sb + OF_W1 + rn * 256 + ((cc ^ (rn & 7)) << 4));
            }
            #pragma unroll
            for (int np = 0; np < 4; ++np) {
                hmma(acc[2 * np],     ah, bw[np][0], bw[np][2]);
                hmma(acc[2 * np + 1], ah, bw[np][1], bw[np][3]);
                hmma(acc[2 * np],     al, bw[np][0], bw[np][2]);
                hmma(acc[2 * np + 1], al, bw[np][1], bw[np][3]);
            }
        }

        // ---- epilogue 1: relu(acc+b1) -> layer-2 A fragments (fp16 hi/lo, registers) ----
        uint32_t a2h[4][4], a2l[4][4];
        #pragma unroll
        for (int kt = 0; kt < 4; ++kt)
            #pragma unroll
            for (int hf = 0; hf < 2; ++hf) {
                const int nt = 2 * kt + hf;
                const float* d = acc[nt];
                const int c0 = nt * 8 + (L & 3) * 2;
                float2 bb = *(float2*)(b1s + c0);
                float h0 = fmaxf(d[0] + bb.x, 0.f), h1 = fmaxf(d[1] + bb.y, 0.f);
                float h2 = fmaxf(d[2] + bb.x, 0.f), h3 = fmaxf(d[3] + bb.y, 0.f);
                a2l[kt][2 * hf]     = cvt16_hilo(h0, h1, a2h[kt][2 * hf]);
                a2l[kt][2 * hf + 1] = cvt16_hilo(h2, h3, a2h[kt][2 * hf + 1]);
            }

        // ---- layer 2 + gate + scatter, 4 chunks of (32 gate + 32 value) cols ----
        #pragma unroll 1
        for (int ch = 0; ch < 4; ++ch) {
            float aG[4][4], aV[4][4];
            #pragma unroll
            for (int nt = 0; nt < 4; ++nt)
                #pragma unroll
                for (int j = 0; j < 4; ++j) { aG[nt][j] = 0.f; aV[nt][j] = 0.f; }

            #pragma unroll
            for (int ks = 0; ks < 4; ++ks) {
                const int cc = ks * 2 + (L >> 4);
                uint32_t bg[2][4], bv[2][4];
                #pragma unroll
                for (int np = 0; np < 2; ++np) {
                    int rg = 32 * ch + np * 16 + (L & 15);
                    int rv = 128 + 32 * ch + np * 16 + (L & 15);
                    ldsm4(bg[np], sb + OF_W2 + rg * 128 + ((cc ^ (rg & 7)) << 4));
                    ldsm4(bv[np], sb + OF_W2 + rv * 128 + ((cc ^ (rv & 7)) << 4));
                }
                #pragma unroll
                for (int np = 0; np < 2; ++np) {
                    hmma(aG[2 * np],     a2h[ks], bg[np][0], bg[np][2]);
                    hmma(aG[2 * np + 1], a2h[ks], bg[np][1], bg[np][3]);
                    hmma(aV[2 * np],     a2h[ks], bv[np][0], bv[np][2]);
                    hmma(aV[2 * np + 1], a2h[ks], bv[np][1], bv[np][3]);
                    hmma(aG[2 * np],     a2l[ks], bg[np][0], bg[np][2]);
                    hmma(aG[2 * np + 1], a2l[ks], bg[np][1], bg[np][3]);
                    hmma(aV[2 * np],     a2l[ks], bv[np][0], bv[np][2]);
                    hmma(aV[2 * np + 1], a2l[ks], bv[np][1], bv[np][3]);
                }
            }

            // ---- epilogue: gated = v*sigmoid(g); pair-exchange -> red.v4 ----
            const int rKeep = m0 + (L >> 2) + (L & 1) * 8;
            const int giK = sGI[rKeep];
            float* const gsK = g_graph_states + (size_t)(giK < 0 ? 0 : giK) * GS;
            #pragma unroll
            for (int nt = 0; nt < 4; ++nt) {
                const int cg = 32 * ch + nt * 8 + (L & 3) * 2;
                float2 bgc = *(float2*)(b2s + cg);
                float2 bvc = *(float2*)(b2s + 128 + cg);
                float gr0 = sigmul(aV[nt][0] + bvc.x, aG[nt][0] + bgc.x);
                float gr1 = sigmul(aV[nt][1] + bvc.y, aG[nt][1] + bgc.y);
                float gs0 = sigmul(aV[nt][2] + bvc.x, aG[nt][2] + bgc.x);
                float gs1 = sigmul(aV[nt][3] + bvc.y, aG[nt][3] + bgc.y);
                const bool even = (L & 1) == 0;
                float s0 = even ? gs0 : gr0;
                float s1 = even ? gs1 : gr1;
                float r0 = __shfl_xor_sync(0xffffffffu, s0, 1);
                float r1 = __shfl_xor_sync(0xffffffffu, s1, 1);
                float mine0 = even ? gr0 : gs0;
                float mine1 = even ? gr1 : gs1;
                float v0 = even ? mine0 : r0;
                float v1 = even ? mine1 : r1;
                float v2 = even ? r0 : mine0;
                float v3 = even ? r1 : mine1;
                const int cb = 32 * ch + nt * 8 + ((L & 3) >> 1) * 4;
                if (giK >= 0) red4(gsK + cb, v0, v1, v2, v3);
            }
        }
        __syncthreads();
    }
}

// ---------------- MLP2 + re-zero accumulator ----------------
__global__ __launch_bounds__(128) void mlp2_rezero_kernel(
    const float* __restrict__ W3, const float* __restrict__ b3,
    const float* __restrict__ W4, const float* __restrict__ b4,
    float* __restrict__ out)
{
    __shared__ float W3s[GS * 32];
    __shared__ float W4s[32 * 16];
    __shared__ float b3s[32];
    __shared__ float b4s[16];

    const int tid = threadIdx.x;
    for (int i = tid; i < (GS * 32) / 4; i += 128) ((float4*)W3s)[i] = ((const float4*)W3)[i];
    for (int i = tid; i < (32 * 16) / 4; i += 128) ((float4*)W4s)[i] = ((const float4*)W4)[i];
    if (tid < 32) b3s[tid] = b3[tid];
    if (tid < 16) b4s[tid] = b4[tid];
    __syncthreads();

    const int g = blockIdx.x * 128 + tid;

    float h3[32];
    #pragma unroll
    for (int j = 0; j < 32; ++j) h3[j] = b3s[j];

    float4* gr = (float4*)(g_graph_states + (size_t)g * GS);
    #pragma unroll 1
    for (int k4 = 0; k4 < GS / 4; ++k4) {
        const float4 gv = gr[k4];
        #pragma unroll
        for (int kk = 0; kk < 4; ++kk) {
            const float gk = (kk == 0) ? gv.x : (kk == 1) ? gv.y : (kk == 2) ? gv.z : gv.w;
            const float* w = &W3s[(k4 * 4 + kk) * 32];
            #pragma unroll
            for (int j = 0; j < 32; ++j) h3[j] += gk * w[j];
        }
    }
    #pragma unroll
    for (int k4 = 0; k4 < GS / 4; ++k4) gr[k4] = make_float4(0.f, 0.f, 0.f, 0.f);

    float o[16];
    #pragma unroll
    for (int j = 0; j < 16; ++j) o[j] = b4s[j];
    #pragma unroll
    for (int k = 0; k < 32; ++k) {
        const float hk = fmaxf(h3[k], 0.f);
        #pragma unroll
        for (int j = 0; j < 16; ++j) o[j] += hk * W4s[k * 16 + j];
    }

    float4* op = (float4*)(out + (size_t)g * 16);
    op[0] = make_float4(o[0],  o[1],  o[2],  o[3]);
    op[1] = make_float4(o[4],  o[5],  o[6],  o[7]);
    op[2] = make_float4(o[8],  o[9],  o[10], o[11]);
    op[3] = make_float4(o[12], o[13], o[14], o[15]);
}

extern "C" void kernel_launch(void* const* d_in, const int* in_sizes, int n_in,
                              void* d_out, int out_size)
{
    const float* X  = (const float*)d_in[0];
    const int*   gi = (const int*)  d_in[1];
    const float* W1 = (const float*)d_in[2];
    const float* b1 = (const float*)d_in[3];
    const float* W2 = (const float*)d_in[4];
    const float* b2 = (const float*)d_in[5];
    const float* W3 = (const float*)d_in[6];
    const float* b3 = (const float*)d_in[7];
    const float* W4 = (const float*)d_in[8];
    const float* b4 = (const float*)d_in[9];
    float* out = (float*)d_out;

    cudaFuncSetAttribute(mma_fused_kernel,
                         cudaFuncAttributeMaxDynamicSharedMemorySize, SMEM_TOTAL);

    prep_kernel<<<64, 256>>>(W1, W2);
    // g_graph_states: zero-initialized at load; re-zeroed by mlp2_rezero each call.
    mma_fused_kernel<<<148, 512, SMEM_TOTAL>>>(X, gi, b1, b2,    0, 1954);
    mma_fused_kernel<<<148, 512, SMEM_TOTAL>>>(X, gi, b1, b2, 1954, N_TILES);
    mlp2_rezero_kernel<<<NG / 128, 128>>>(W3, b3, W4, b4, out);
}

// round 14
// speedup vs baseline: 1.7448x; 1.2541x over previous
#include <cuda_runtime.h>
#include <cuda_fp16.h>
#include <cstdint>

#define N_NODES 1000000
#define D_IN    128
#define H1      64
#define D2C     256
#define GS      128
#define NG      4096
#define TILE_M  256
#define N_TILES ((N_NODES + TILE_M - 1) / TILE_M)   // 3907

__device__ float g_graph_states[NG * GS];
__device__ __align__(16) __half gW1[H1 * D_IN];    // [n][k] = fp16(W1[k][n])
__device__ __align__(16) __half gW2[D2C * H1];     // [n][k] = fp16(W2[k][n])

// ---------------- helpers ----------------
__device__ __forceinline__ uint32_t smem_u32(const void* p) {
    uint32_t a;
    asm("{ .reg .u64 t; cvta.to.shared.u64 t, %1; cvt.u32.u64 %0, t; }" : "=r"(a) : "l"(p));
    return a;
}
__device__ __forceinline__ void ldsm4(uint32_t* r, uint32_t addr) {
    asm volatile("ldmatrix.sync.aligned.m8n8.x4.shared.b16 {%0,%1,%2,%3}, [%4];"
                 : "=r"(r[0]), "=r"(r[1]), "=r"(r[2]), "=r"(r[3]) : "r"(addr));
}
__device__ __forceinline__ void hmma(float* d, const uint32_t* a, uint32_t b0, uint32_t b1) {
    asm volatile("mma.sync.aligned.m16n8k16.row.col.f32.f16.f16.f32 "
                 "{%0,%1,%2,%3}, {%4,%5,%6,%7}, {%8,%9}, {%0,%1,%2,%3};"
                 : "+f"(d[0]), "+f"(d[1]), "+f"(d[2]), "+f"(d[3])
                 : "r"(a[0]), "r"(a[1]), "r"(a[2]), "r"(a[3]), "r"(b0), "r"(b1));
}
__device__ __forceinline__ uint32_t cvt16(float f0, float f1) {
    __half2 h = __floats2half2_rn(f0, f1);
    return *(uint32_t*)&h;
}
__device__ __forceinline__ void red4(float* p, float x, float y, float z, float w) {
    asm volatile("red.global.add.v4.f32 [%0], {%1,%2,%3,%4};"
                 :: "l"(p), "f"(x), "f"(y), "f"(z), "f"(w) : "memory");
}
// v * sigmoid(g) via single-MUFU tanh
__device__ __forceinline__ float sigmul(float v, float g) {
    float t;
    asm("tanh.approx.f32 %0, %1;" : "=f"(t) : "f"(g * 0.5f));
    return v * (0.5f + 0.5f * t);
}

// ---------------- prep: W transpose + fp16 ----------------
__global__ void prep_kernel(const float* __restrict__ W1, const float* __restrict__ W2) {
    int i = blockIdx.x * blockDim.x + threadIdx.x;
    if (i < H1 * D_IN) {
        int n = i >> 7, k = i & 127;
        gW1[i] = __float2half_rn(W1[k * H1 + n]);
    }
    if (i < D2C * H1) {
        int n = i >> 6, k = i & 63;
        gW2[i] = __float2half_rn(W2[k * D2C + n]);
    }
}

// ---------------- SMEM layout (bytes) ----------------
#define OF_XH  0          // 256 rows x 256B (swizzled, 16 chunks)
#define OF_W1  65536      // 64 rows x 256B
#define OF_W2  81920      // 256 rows x 128B (8 chunks)
#define OF_B1  114688     // 64 f32
#define OF_B2  114944     // 256 f32
#define OF_GI  115968     // 256 int
#define SMEM_TOTAL 116992

// ---------------- fused HMMA kernel: 512 threads (16 warps), TILE_M=256 ----------------
__global__ __launch_bounds__(512, 1)
void mma_fused_kernel(const float* __restrict__ X, const int* __restrict__ gidx,
                      const float* __restrict__ b1, const float* __restrict__ b2,
                      int tile_begin, int tile_end)
{
    extern __shared__ char smem[];
    const uint32_t sb = smem_u32(smem);
    const int tid = threadIdx.x;
    const int L   = tid & 31;
    const int m0  = (tid >> 5) * 16;            // warp's 16 rows (16 warps x 16 = 256)
    float* b1s = (float*)(smem + OF_B1);
    float* b2s = (float*)(smem + OF_B2);
    int*   sGI = (int*)(smem + OF_GI);

    // ---- stage weights (swizzled for ldmatrix) + biases ----
    for (int i = tid; i < H1 * 16; i += 512) {            // W1: 64 rows x 16 chunks
        int n = i >> 4, c = i & 15;
        uint32_t off = n * 256 + ((c ^ (n & 7)) << 4);
        *(uint4*)(smem + OF_W1 + off) = *(const uint4*)(gW1 + n * D_IN + c * 8);
    }
    for (int i = tid; i < D2C * 8; i += 512) {            // W2: 256 rows x 8 chunks
        int n = i >> 3, c = i & 7;
        uint32_t off = n * 128 + ((c ^ (n & 7)) << 4);
        *(uint4*)(smem + OF_W2 + off) = *(const uint4*)(gW2 + n * H1 + c * 8);
    }
    if (tid < 64) b1s[tid] = b1[tid];
    if (tid >= 64 && tid < 320) b2s[tid - 64] = b2[tid - 64];
    __syncthreads();

    for (int tile = tile_begin + blockIdx.x; tile < tile_end; tile += gridDim.x) {
        // ---- phase A: 2 threads per X row (8 chunks each) -> fp16 SMEM ----
        const int row  = tid >> 1;
        const int half = tid & 1;
        const int node = tile * TILE_M + row;
        const bool valid = node < N_NODES;
        if (half == 0) sGI[row] = valid ? __ldg(&gidx[node]) : -1;
        const float4* xr = (const float4*)(X + (size_t)node * D_IN);
        #pragma unroll 4
        for (int cc8 = 0; cc8 < 8; ++cc8) {
            const int c = half * 8 + cc8;
            uint4 H = make_uint4(0, 0, 0, 0);
            if (valid) {
                float4 a = __ldg(&xr[2 * c]), b = __ldg(&xr[2 * c + 1]);
                H.x = cvt16(a.x, a.y);
                H.y = cvt16(a.z, a.w);
                H.z = cvt16(b.x, b.y);
                H.w = cvt16(b.z, b.w);
            }
            uint32_t off = row * 256 + ((c ^ (row & 7)) << 4);
            *(uint4*)(smem + OF_XH + off) = H;
        }
        __syncthreads();

        // ---- layer 1: warp's [16,128] @ W1^T[128,64], single fp16 product ----
        float acc[8][4];
        #pragma unroll
        for (int nt = 0; nt < 8; ++nt)
            #pragma unroll
            for (int j = 0; j < 4; ++j) acc[nt][j] = 0.f;

        #pragma unroll 1
        for (int ks = 0; ks < 8; ++ks) {
            const int cc = ks * 2 + (L >> 4);
            uint32_t ah[4], bw[4][4];
            {
                int r = m0 + (L & 15);
                uint32_t off = r * 256 + ((cc ^ (r & 7)) << 4);
                ldsm4(ah, sb + OF_XH + off);
            }
            #pragma unroll
            for (int np = 0; np < 4; ++np) {
                int rn = np * 16 + (L & 15);
                ldsm4(bw[np], sb + OF_W1 + rn * 256 + ((cc ^ (rn & 7)) << 4));
            }
            #pragma unroll
            for (int np = 0; np < 4; ++np) {
                hmma(acc[2 * np],     ah, bw[np][0], bw[np][2]);
                hmma(acc[2 * np + 1], ah, bw[np][1], bw[np][3]);
            }
        }

        // ---- epilogue 1: relu(acc+b1) -> layer-2 A fragments (fp16, registers) ----
        uint32_t a2h[4][4];
        #pragma unroll
        for (int kt = 0; kt < 4; ++kt)
            #pragma unroll
            for (int hf = 0; hf < 2; ++hf) {
                const int nt = 2 * kt + hf;
                const float* d = acc[nt];
                const int c0 = nt * 8 + (L & 3) * 2;
                float2 bb = *(float2*)(b1s + c0);
                float h0 = fmaxf(d[0] + bb.x, 0.f), h1 = fmaxf(d[1] + bb.y, 0.f);
                float h2 = fmaxf(d[2] + bb.x, 0.f), h3 = fmaxf(d[3] + bb.y, 0.f);
                a2h[kt][2 * hf]     = cvt16(h0, h1);
                a2h[kt][2 * hf + 1] = cvt16(h2, h3);
            }

        // ---- layer 2 + gate + scatter, 4 chunks of (32 gate + 32 value) cols ----
        #pragma unroll 1
        for (int ch = 0; ch < 4; ++ch) {
            float aG[4][4], aV[4][4];
            #pragma unroll
            for (int nt = 0; nt < 4; ++nt)
                #pragma unroll
                for (int j = 0; j < 4; ++j) { aG[nt][j] = 0.f; aV[nt][j] = 0.f; }

            #pragma unroll
            for (int ks = 0; ks < 4; ++ks) {
                const int cc = ks * 2 + (L >> 4);
                uint32_t bg[2][4], bv[2][4];
                #pragma unroll
                for (int np = 0; np < 2; ++np) {
                    int rg = 32 * ch + np * 16 + (L & 15);
                    int rv = 128 + 32 * ch + np * 16 + (L & 15);
                    ldsm4(bg[np], sb + OF_W2 + rg * 128 + ((cc ^ (rg & 7)) << 4));
                    ldsm4(bv[np], sb + OF_W2 + rv * 128 + ((cc ^ (rv & 7)) << 4));
                }
                #pragma unroll
                for (int np = 0; np < 2; ++np) {
                    hmma(aG[2 * np],     a2h[ks], bg[np][0], bg[np][2]);
                    hmma(aG[2 * np + 1], a2h[ks], bg[np][1], bg[np][3]);
                    hmma(aV[2 * np],     a2h[ks], bv[np][0], bv[np][2]);
                    hmma(aV[2 * np + 1], a2h[ks], bv[np][1], bv[np][3]);
                }
            }

            // ---- epilogue: gated = v*sigmoid(g); pair-exchange -> red.v4 ----
            const int rKeep = m0 + (L >> 2) + (L & 1) * 8;
            const int giK = sGI[rKeep];
            float* const gsK = g_graph_states + (size_t)(giK < 0 ? 0 : giK) * GS;
            #pragma unroll
            for (int nt = 0; nt < 4; ++nt) {
                const int cg = 32 * ch + nt * 8 + (L & 3) * 2;
                float2 bgc = *(float2*)(b2s + cg);
                float2 bvc = *(float2*)(b2s + 128 + cg);
                float gr0 = sigmul(aV[nt][0] + bvc.x, aG[nt][0] + bgc.x);
                float gr1 = sigmul(aV[nt][1] + bvc.y, aG[nt][1] + bgc.y);
                float gs0 = sigmul(aV[nt][2] + bvc.x, aG[nt][2] + bgc.x);
                float gs1 = sigmul(aV[nt][3] + bvc.y, aG[nt][3] + bgc.y);
                const bool even = (L & 1) == 0;
                float s0 = even ? gs0 : gr0;
                float s1 = even ? gs1 : gr1;
                float r0 = __shfl_xor_sync(0xffffffffu, s0, 1);
                float r1 = __shfl_xor_sync(0xffffffffu, s1, 1);
                float mine0 = even ? gr0 : gs0;
                float mine1 = even ? gr1 : gs1;
                float v0 = even ? mine0 : r0;
                float v1 = even ? mine1 : r1;
                float v2 = even ? r0 : mine0;
                float v3 = even ? r1 : mine1;
                const int cb = 32 * ch + nt * 8 + ((L & 3) >> 1) * 4;
                if (giK >= 0) red4(gsK + cb, v0, v1, v2, v3);
            }
        }
        __syncthreads();
    }
}

// ---------------- MLP2 + re-zero accumulator ----------------
__global__ __launch_bounds__(128) void mlp2_rezero_kernel(
    const float* __restrict__ W3, const float* __restrict__ b3,
    const float* __restrict__ W4, const float* __restrict__ b4,
    float* __restrict__ out)
{
    __shared__ float W3s[GS * 32];
    __shared__ float W4s[32 * 16];
    __shared__ float b3s[32];
    __shared__ float b4s[16];

    const int tid = threadIdx.x;
    for (int i = tid; i < (GS * 32) / 4; i += 128) ((float4*)W3s)[i] = ((const float4*)W3)[i];
    for (int i = tid; i < (32 * 16) / 4; i += 128) ((float4*)W4s)[i] = ((const float4*)W4)[i];
    if (tid < 32) b3s[tid] = b3[tid];
    if (tid < 16) b4s[tid] = b4[tid];
    __syncthreads();

    const int g = blockIdx.x * 128 + tid;

    float h3[32];
    #pragma unroll
    for (int j = 0; j < 32; ++j) h3[j] = b3s[j];

    float4* gr = (float4*)(g_graph_states + (size_t)g * GS);
    #pragma unroll 1
    for (int k4 = 0; k4 < GS / 4; ++k4) {
        const float4 gv = gr[k4];
        #pragma unroll
        for (int kk = 0; kk < 4; ++kk) {
            const float gk = (kk == 0) ? gv.x : (kk == 1) ? gv.y : (kk == 2) ? gv.z : gv.w;
            const float* w = &W3s[(k4 * 4 + kk) * 32];
            #pragma unroll
            for (int j = 0; j < 32; ++j) h3[j] += gk * w[j];
        }
    }
    #pragma unroll
    for (int k4 = 0; k4 < GS / 4; ++k4) gr[k4] = make_float4(0.f, 0.f, 0.f, 0.f);

    float o[16];
    #pragma unroll
    for (int j = 0; j < 16; ++j) o[j] = b4s[j];
    #pragma unroll
    for (int k = 0; k < 32; ++k) {
        const float hk = fmaxf(h3[k], 0.f);
        #pragma unroll
        for (int j = 0; j < 16; ++j) o[j] += hk * W4s[k * 16 + j];
    }

    float4* op = (float4*)(out + (size_t)g * 16);
    op[0] = make_float4(o[0],  o[1],  o[2],  o[3]);
    op[1] = make_float4(o[4],  o[5],  o[6],  o[7]);
    op[2] = make_float4(o[8],  o[9],  o[10], o[11]);
    op[3] = make_float4(o[12], o[13], o[14], o[15]);
}

extern "C" void kernel_launch(void* const* d_in, const int* in_sizes, int n_in,
                              void* d_out, int out_size)
{
    const float* X  = (const float*)d_in[0];
    const int*   gi = (const int*)  d_in[1];
    const float* W1 = (const float*)d_in[2];
    const float* b1 = (const float*)d_in[3];
    const float* W2 = (const float*)d_in[4];
    const float* b2 = (const float*)d_in[5];
    const float* W3 = (const float*)d_in[6];
    const float* b3 = (const float*)d_in[7];
    const float* W4 = (const float*)d_in[8];
    const float* b4 = (const float*)d_in[9];
    float* out = (float*)d_out;

    cudaFuncSetAttribute(mma_fused_kernel,
                         cudaFuncAttributeMaxDynamicSharedMemorySize, SMEM_TOTAL);

    prep_kernel<<<64, 256>>>(W1, W2);
    // g_graph_states: zero-initialized at load; re-zeroed by mlp2_rezero each call.
    mma_fused_kernel<<<148, 512, SMEM_TOTAL>>>(X, gi, b1, b2,    0, 1954);
    mma_fused_kernel<<<148, 512, SMEM_TOTAL>>>(X, gi, b1, b2, 1954, N_TILES);
    mlp2_rezero_kernel<<<NG / 128, 128>>>(W3, b3, W4, b4, out);
}

// round 15
// speedup vs baseline: 1.7466x; 1.0010x over previous
#include <cuda_runtime.h>
#include <cuda_fp16.h>
#include <cstdint>

#define N_NODES 1000000
#define D_IN    128
#define H1      64
#define D2C     256
#define GS      128
#define NG      4096
#define TILE_M  256
#define N_TILES ((N_NODES + TILE_M - 1) / TILE_M)   // 3907

__device__ float g_graph_states[NG * GS];
__device__ __align__(16) __half gW1[H1 * D_IN];    // [n][k] = fp16(W1[k][n])
__device__ __align__(16) __half gW2[D2C * H1];     // [n][k] = fp16(W2[k][n])

// ---------------- helpers ----------------
__device__ __forceinline__ uint32_t smem_u32(const void* p) {
    uint32_t a;
    asm("{ .reg .u64 t; cvta.to.shared.u64 t, %1; cvt.u32.u64 %0, t; }" : "=r"(a) : "l"(p));
    return a;
}
__device__ __forceinline__ void ldsm4(uint32_t* r, uint32_t addr) {
    asm volatile("ldmatrix.sync.aligned.m8n8.x4.shared.b16 {%0,%1,%2,%3}, [%4];"
                 : "=r"(r[0]), "=r"(r[1]), "=r"(r[2]), "=r"(r[3]) : "r"(addr));
}
__device__ __forceinline__ void hmma(float* d, const uint32_t* a, uint32_t b0, uint32_t b1) {
    asm volatile("mma.sync.aligned.m16n8k16.row.col.f32.f16.f16.f32 "
                 "{%0,%1,%2,%3}, {%4,%5,%6,%7}, {%8,%9}, {%0,%1,%2,%3};"
                 : "+f"(d[0]), "+f"(d[1]), "+f"(d[2]), "+f"(d[3])
                 : "r"(a[0]), "r"(a[1]), "r"(a[2]), "r"(a[3]), "r"(b0), "r"(b1));
}
__device__ __forceinline__ uint32_t cvt16(float f0, float f1) {
    __half2 h = __floats2half2_rn(f0, f1);
    return *(uint32_t*)&h;
}
__device__ __forceinline__ void red4(float* p, float x, float y, float z, float w) {
    asm volatile("red.global.add.v4.f32 [%0], {%1,%2,%3,%4};"
                 :: "l"(p), "f"(x), "f"(y), "f"(z), "f"(w) : "memory");
}
// v * sigmoid(g) via single-MUFU tanh
__device__ __forceinline__ float sigmul(float v, float g) {
    float t;
    asm("tanh.approx.f32 %0, %1;" : "=f"(t) : "f"(g * 0.5f));
    return v * (0.5f + 0.5f * t);
}

// ---------------- prep: W transpose + fp16 ----------------
__global__ void prep_kernel(const float* __restrict__ W1, const float* __restrict__ W2) {
    int i = blockIdx.x * blockDim.x + threadIdx.x;
    if (i < H1 * D_IN) {
        int n = i >> 7, k = i & 127;
        gW1[i] = __float2half_rn(W1[k * H1 + n]);
    }
    if (i < D2C * H1) {
        int n = i >> 6, k = i & 63;
        gW2[i] = __float2half_rn(W2[k * D2C + n]);
    }
}

// ---------------- SMEM layout (bytes) ----------------
#define OF_XH  0          // 2 buffers x (256 rows x 256B swizzled)
#define XH_BUF 65536
#define OF_W1  131072     // 64 rows x 256B
#define OF_W2  147456     // 256 rows x 128B (8 chunks)
#define OF_B1  180224     // 64 f32
#define OF_B2  180480     // 256 f32
#define OF_GI  181504     // 2 buffers x 256 int
#define SMEM_TOTAL 183552

// phase A: stage one tile's X rows (fp16) + gidx into buffer bsel
__device__ __forceinline__ void stage_tile(char* smem, const float* __restrict__ X,
                                           const int* __restrict__ gidx,
                                           int tile, int bsel, int tid)
{
    const int row  = tid >> 1;
    const int half = tid & 1;
    const int node = tile * TILE_M + row;
    const bool valid = node < N_NODES;
    if (half == 0)
        ((int*)(smem + OF_GI))[bsel * 256 + row] = valid ? __ldg(&gidx[node]) : -1;
    const float4* xr = (const float4*)(X + (size_t)node * D_IN);
    char* xb = smem + OF_XH + bsel * XH_BUF;
    #pragma unroll 4
    for (int cc8 = 0; cc8 < 8; ++cc8) {
        const int c = half * 8 + cc8;
        uint4 H = make_uint4(0, 0, 0, 0);
        if (valid) {
            float4 a = __ldg(&xr[2 * c]), b = __ldg(&xr[2 * c + 1]);
            H.x = cvt16(a.x, a.y);
            H.y = cvt16(a.z, a.w);
            H.z = cvt16(b.x, b.y);
            H.w = cvt16(b.z, b.w);
        }
        *(uint4*)(xb + row * 256 + ((c ^ (row & 7)) << 4)) = H;
    }
}

// ---------------- fused HMMA kernel: 512 threads, double-buffered ----------------
__global__ __launch_bounds__(512, 1)
void mma_fused_kernel(const float* __restrict__ X, const int* __restrict__ gidx,
                      const float* __restrict__ b1, const float* __restrict__ b2,
                      int tile_begin, int tile_end)
{
    extern __shared__ char smem[];
    const uint32_t sb = smem_u32(smem);
    const int tid = threadIdx.x;
    const int L   = tid & 31;
    const int m0  = (tid >> 5) * 16;            // warp's 16 rows (16 warps x 16 = 256)
    float* b1s = (float*)(smem + OF_B1);
    float* b2s = (float*)(smem + OF_B2);

    // ---- stage weights (swizzled for ldmatrix) + biases ----
    for (int i = tid; i < H1 * 16; i += 512) {            // W1: 64 rows x 16 chunks
        int n = i >> 4, c = i & 15;
        uint32_t off = n * 256 + ((c ^ (n & 7)) << 4);
        *(uint4*)(smem + OF_W1 + off) = *(const uint4*)(gW1 + n * D_IN + c * 8);
    }
    for (int i = tid; i < D2C * 8; i += 512) {            // W2: 256 rows x 8 chunks
        int n = i >> 3, c = i & 7;
        uint32_t off = n * 128 + ((c ^ (n & 7)) << 4);
        *(uint4*)(smem + OF_W2 + off) = *(const uint4*)(gW2 + n * H1 + c * 8);
    }
    if (tid < 64) b1s[tid] = b1[tid];
    if (tid >= 64 && tid < 320) b2s[tid - 64] = b2[tid - 64];

    // prologue: stage first tile into buffer 0
    stage_tile(smem, X, gidx, tile_begin + blockIdx.x, 0, tid);
    __syncthreads();

    int buf = 0;
    for (int tile = tile_begin + blockIdx.x; tile < tile_end; tile += gridDim.x) {
        // ---- prefetch next tile into the other buffer (overlaps compute) ----
        const int nxt = tile + gridDim.x;
        if (nxt < tile_end) stage_tile(smem, X, gidx, nxt, buf ^ 1, tid);

        const uint32_t xbase = sb + OF_XH + buf * XH_BUF;
        const int* sGIb = (const int*)(smem + OF_GI) + buf * 256;

        // ---- layer 1: warp's [16,128] @ W1^T[128,64], single fp16 product ----
        float acc[8][4];
        #pragma unroll
        for (int nt = 0; nt < 8; ++nt)
            #pragma unroll
            for (int j = 0; j < 4; ++j) acc[nt][j] = 0.f;

        #pragma unroll 1
        for (int ks = 0; ks < 8; ++ks) {
            const int cc = ks * 2 + (L >> 4);
            uint32_t ah[4], bw[4][4];
            {
                int r = m0 + (L & 15);
                ldsm4(ah, xbase + r * 256 + ((cc ^ (r & 7)) << 4));
            }
            #pragma unroll
            for (int np = 0; np < 4; ++np) {
                int rn = np * 16 + (L & 15);
                ldsm4(bw[np], sb + OF_W1 + rn * 256 + ((cc ^ (rn & 7)) << 4));
            }
            #pragma unroll
            for (int np = 0; np < 4; ++np) {
                hmma(acc[2 * np],     ah, bw[np][0], bw[np][2]);
                hmma(acc[2 * np + 1], ah, bw[np][1], bw[np][3]);
            }
        }

        // ---- epilogue 1: relu(acc+b1) -> layer-2 A fragments (fp16, registers) ----
        uint32_t a2h[4][4];
        #pragma unroll
        for (int kt = 0; kt < 4; ++kt)
            #pragma unroll
            for (int hf = 0; hf < 2; ++hf) {
                const int nt = 2 * kt + hf;
                const float* d = acc[nt];
                const int c0 = nt * 8 + (L & 3) * 2;
                float2 bb = *(float2*)(b1s + c0);
                float h0 = fmaxf(d[0] + bb.x, 0.f), h1 = fmaxf(d[1] + bb.y, 0.f);
                float h2 = fmaxf(d[2] + bb.x, 0.f), h3 = fmaxf(d[3] + bb.y, 0.f);
                a2h[kt][2 * hf]     = cvt16(h0, h1);
                a2h[kt][2 * hf + 1] = cvt16(h2, h3);
            }

        // ---- layer 2 + gate + scatter, 4 chunks of (32 gate + 32 value) cols ----
        #pragma unroll 1
        for (int ch = 0; ch < 4; ++ch) {
            float aG[4][4], aV[4][4];
            #pragma unroll
            for (int nt = 0; nt < 4; ++nt)
                #pragma unroll
                for (int j = 0; j < 4; ++j) { aG[nt][j] = 0.f; aV[nt][j] = 0.f; }

            #pragma unroll
            for (int ks = 0; ks < 4; ++ks) {
                const int cc = ks * 2 + (L >> 4);
                uint32_t bg[2][4], bv[2][4];
                #pragma unroll
                for (int np = 0; np < 2; ++np) {
                    int rg = 32 * ch + np * 16 + (L & 15);
                    int rv = 128 + 32 * ch + np * 16 + (L & 15);
                    ldsm4(bg[np], sb + OF_W2 + rg * 128 + ((cc ^ (rg & 7)) << 4));
                    ldsm4(bv[np], sb + OF_W2 + rv * 128 + ((cc ^ (rv & 7)) << 4));
                }
                #pragma unroll
                for (int np = 0; np < 2; ++np) {
                    hmma(aG[2 * np],     a2h[ks], bg[np][0], bg[np][2]);
                    hmma(aG[2 * np + 1], a2h[ks], bg[np][1], bg[np][3]);
                    hmma(aV[2 * np],     a2h[ks], bv[np][0], bv[np][2]);
                    hmma(aV[2 * np + 1], a2h[ks], bv[np][1], bv[np][3]);
                }
            }

            // ---- epilogue: gated = v*sigmoid(g); pair-exchange -> red.v4 ----
            const int rKeep = m0 + (L >> 2) + (L & 1) * 8;
            const int giK = sGIb[rKeep];
            float* const gsK = g_graph_states + (size_t)(giK < 0 ? 0 : giK) * GS;
            #pragma unroll
            for (int nt = 0; nt < 4; ++nt) {
                const int cg = 32 * ch + nt * 8 + (L & 3) * 2;
                float2 bgc = *(float2*)(b2s + cg);
                float2 bvc = *(float2*)(b2s + 128 + cg);
                float gr0 = sigmul(aV[nt][0] + bvc.x, aG[nt][0] + bgc.x);
                float gr1 = sigmul(aV[nt][1] + bvc.y, aG[nt][1] + bgc.y);
                float gs0 = sigmul(aV[nt][2] + bvc.x, aG[nt][2] + bgc.x);
                float gs1 = sigmul(aV[nt][3] + bvc.y, aG[nt][3] + bgc.y);
                const bool even = (L & 1) == 0;
                float s0 = even ? gs0 : gr0;
                float s1 = even ? gs1 : gr1;
                float r0 = __shfl_xor_sync(0xffffffffu, s0, 1);
                float r1 = __shfl_xor_sync(0xffffffffu, s1, 1);
                float mine0 = even ? gr0 : gs0;
                float mine1 = even ? gr1 : gs1;
                float v0 = even ? mine0 : r0;
                float v1 = even ? mine1 : r1;
                float v2 = even ? r0 : mine0;
                float v3 = even ? r1 : mine1;
                const int cb = 32 * ch + nt * 8 + ((L & 3) >> 1) * 4;
                if (giK >= 0) red4(gsK + cb, v0, v1, v2, v3);
            }
        }
        __syncthreads();       // staging of buf^1 done; reads of buf done
        buf ^= 1;
    }
}

// ---------------- MLP2 + re-zero accumulator ----------------
__global__ __launch_bounds__(128) void mlp2_rezero_kernel(
    const float* __restrict__ W3, const float* __restrict__ b3,
    const float* __restrict__ W4, const float* __restrict__ b4,
    float* __restrict__ out)
{
    __shared__ float W3s[GS * 32];
    __shared__ float W4s[32 * 16];
    __shared__ float b3s[32];
    __shared__ float b4s[16];

    const int tid = threadIdx.x;
    for (int i = tid; i < (GS * 32) / 4; i += 128) ((float4*)W3s)[i] = ((const float4*)W3)[i];
    for (int i = tid; i < (32 * 16) / 4; i += 128) ((float4*)W4s)[i] = ((const float4*)W4)[i];
    if (tid < 32) b3s[tid] = b3[tid];
    if (tid < 16) b4s[tid] = b4[tid];
    __syncthreads();

    const int g = blockIdx.x * 128 + tid;

    float h3[32];
    #pragma unroll
    for (int j = 0; j < 32; ++j) h3[j] = b3s[j];

    float4* gr = (float4*)(g_graph_states + (size_t)g * GS);
    #pragma unroll 1
    for (int k4 = 0; k4 < GS / 4; ++k4) {
        const float4 gv = gr[k4];
        #pragma unroll
        for (int kk = 0; kk < 4; ++kk) {
            const float gk = (kk == 0) ? gv.x : (kk == 1) ? gv.y : (kk == 2) ? gv.z : gv.w;
            const float* w = &W3s[(k4 * 4 + kk) * 32];
            #pragma unroll
            for (int j = 0; j < 32; ++j) h3[j] += gk * w[j];
        }
    }
    #pragma unroll
    for (int k4 = 0; k4 < GS / 4; ++k4) gr[k4] = make_float4(0.f, 0.f, 0.f, 0.f);

    float o[16];
    #pragma unroll
    for (int j = 0; j < 16; ++j) o[j] = b4s[j];
    #pragma unroll
    for (int k = 0; k < 32; ++k) {
        const float hk = fmaxf(h3[k], 0.f);
        #pragma unroll
        for (int j = 0; j < 16; ++j) o[j] += hk * W4s[k * 16 + j];
    }

    float4* op = (float4*)(out + (size_t)g * 16);
    op[0] = make_float4(o[0],  o[1],  o[2],  o[3]);
    op[1] = make_float4(o[4],  o[5],  o[6],  o[7]);
    op[2] = make_float4(o[8],  o[9],  o[10], o[11]);
    op[3] = make_float4(o[12], o[13], o[14], o[15]);
}

extern "C" void kernel_launch(void* const* d_in, const int* in_sizes, int n_in,
                              void* d_out, int out_size)
{
    const float* X  = (const float*)d_in[0];
    const int*   gi = (const int*)  d_in[1];
    const float* W1 = (const float*)d_in[2];
    const float* b1 = (const float*)d_in[3];
    const float* W2 = (const float*)d_in[4];
    const float* b2 = (const float*)d_in[5];
    const float* W3 = (const float*)d_in[6];
    const float* b3 = (const float*)d_in[7];
    const float* W4 = (const float*)d_in[8];
    const float* b4 = (const float*)d_in[9];
    float* out = (float*)d_out;

    cudaFuncSetAttribute(mma_fused_kernel,
                         cudaFuncAttributeMaxDynamicSharedMemorySize, SMEM_TOTAL);

    prep_kernel<<<64, 256>>>(W1, W2);
    // g_graph_states: zero-initialized at load; re-zeroed by mlp2_rezero each call.
    mma_fused_kernel<<<148, 512, SMEM_TOTAL>>>(X, gi, b1, b2, 0, N_TILES);
    mlp2_rezero_kernel<<<NG / 128, 128>>>(W3, b3, W4, b4, out);
}

// round 17
// speedup vs baseline: 1.8905x; 1.0824x over previous
#include <cuda_runtime.h>
#include <cuda_fp16.h>
#include <cstdint>

#define N_NODES 1000000
#define D_IN    128
#define H1      64
#define D2C     256
#define GS      128
#define NG      4096
#define TILE_M  128
#define N_TILES ((N_NODES + TILE_M - 1) / TILE_M)   // 7813

__device__ float g_graph_states[NG * GS];
__device__ __align__(16) __half gW1[H1 * D_IN];    // [n][k] = fp16(W1[k][n])
__device__ __align__(16) __half gW2[D2C * H1];     // [n][k] = fp16(W2[k][n])

// ---------------- helpers ----------------
__device__ __forceinline__ uint32_t smem_u32(const void* p) {
    uint32_t a;
    asm("{ .reg .u64 t; cvta.to.shared.u64 t, %1; cvt.u32.u64 %0, t; }" : "=r"(a) : "l"(p));
    return a;
}
__device__ __forceinline__ void ldsm4(uint32_t* r, uint32_t addr) {
    asm volatile("ldmatrix.sync.aligned.m8n8.x4.shared.b16 {%0,%1,%2,%3}, [%4];"
                 : "=r"(r[0]), "=r"(r[1]), "=r"(r[2]), "=r"(r[3]) : "r"(addr));
}
__device__ __forceinline__ void hmma(float* d, const uint32_t* a, uint32_t b0, uint32_t b1) {
    asm volatile("mma.sync.aligned.m16n8k16.row.col.f32.f16.f16.f32 "
                 "{%0,%1,%2,%3}, {%4,%5,%6,%7}, {%8,%9}, {%0,%1,%2,%3};"
                 : "+f"(d[0]), "+f"(d[1]), "+f"(d[2]), "+f"(d[3])
                 : "r"(a[0]), "r"(a[1]), "r"(a[2]), "r"(a[3]), "r"(b0), "r"(b1));
}
__device__ __forceinline__ uint32_t cvt16(float f0, float f1) {
    __half2 h = __floats2half2_rn(f0, f1);
    return *(uint32_t*)&h;
}
__device__ __forceinline__ void red2(float* p, float x, float y) {
    asm volatile("red.global.add.v2.f32 [%0], {%1,%2};" :: "l"(p), "f"(x), "f"(y) : "memory");
}
// v * sigmoid(g) via single-MUFU tanh
__device__ __forceinline__ float sigmul(float v, float g) {
    float t;
    asm("tanh.approx.f32 %0, %1;" : "=f"(t) : "f"(g * 0.5f));
    return v * (0.5f + 0.5f * t);
}

// ---------------- prep: W transpose + fp16 ----------------
__global__ void prep_kernel(const float* __restrict__ W1, const float* __restrict__ W2) {
    int i = blockIdx.x * blockDim.x + threadIdx.x;
    if (i < H1 * D_IN) {
        int n = i >> 7, k = i & 127;
        gW1[i] = __float2half_rn(W1[k * H1 + n]);
    }
    if (i < D2C * H1) {
        int n = i >> 6, k = i & 63;
        gW2[i] = __float2half_rn(W2[k * D2C + n]);
    }
}

// no-op: shifts ncu's capture index (-s 5) onto the fused kernel below
__global__ void dummy_kernel() {}

// ---------------- SMEM layout (bytes), per CTA ----------------
#define OF_XH  0          // 128 rows x 256B (swizzled, 16 chunks)
#define OF_W1  32768      // 64 rows x 256B
#define OF_W2  49152      // 256 rows x 128B (8 chunks)
#define OF_B1  81920      // 64 f32
#define OF_B2  82176      // 256 f32
#define OF_GI  83200      // 128 int
#define SMEM_TOTAL 83712

// ---------------- fused HMMA kernel: 256 threads, 2 CTAs/SM, TILE_M=128 ----------------
__global__ __launch_bounds__(256, 2)
void mma_fused_kernel(const float* __restrict__ X, const int* __restrict__ gidx,
                      const float* __restrict__ b1, const float* __restrict__ b2,
                      int tile_begin, int tile_end)
{
    extern __shared__ char smem[];
    const uint32_t sb = smem_u32(smem);
    const int tid = threadIdx.x;
    const int L   = tid & 31;
    const int m0  = (tid >> 5) * 16;            // warp's 16 rows (8 warps x 16 = 128)
    float* b1s = (float*)(smem + OF_B1);
    float* b2s = (float*)(smem + OF_B2);
    int*   sGI = (int*)(smem + OF_GI);

    // ---- stage weights (swizzled for ldmatrix) + biases ----
    for (int i = tid; i < H1 * 16; i += 256) {            // W1: 64 rows x 16 chunks
        int n = i >> 4, c = i & 15;
        uint32_t off = n * 256 + ((c ^ (n & 7)) << 4);
        *(uint4*)(smem + OF_W1 + off) = *(const uint4*)(gW1 + n * D_IN + c * 8);
    }
    for (int i = tid; i < D2C * 8; i += 256) {            // W2: 256 rows x 8 chunks
        int n = i >> 3, c = i & 7;
        uint32_t off = n * 128 + ((c ^ (n & 7)) << 4);
        *(uint4*)(smem + OF_W2 + off) = *(const uint4*)(gW2 + n * H1 + c * 8);
    }
    if (tid < 64) b1s[tid] = b1[tid];
    b2s[tid] = b2[tid];                                   // ALL 256 entries staged
    __syncthreads();

    for (int tile = tile_begin + blockIdx.x; tile < tile_end; tile += gridDim.x) {
        // ---- phase A: 2 threads per X row (8 chunks each) -> fp16 SMEM ----
        const int row  = tid >> 1;
        const int half = tid & 1;
        const int node = tile * TILE_M + row;
        const bool valid = node < N_NODES;
        if (half == 0) sGI[row] = valid ? __ldg(&gidx[node]) : -1;
        const float4* xr = (const float4*)(X + (size_t)node * D_IN);
        #pragma unroll 4
        for (int cc8 = 0; cc8 < 8; ++cc8) {
            const int c = half * 8 + cc8;
            uint4 H = make_uint4(0, 0, 0, 0);
            if (valid) {
                float4 a = __ldg(&xr[2 * c]), b = __ldg(&xr[2 * c + 1]);
                H.x = cvt16(a.x, a.y);
                H.y = cvt16(a.z, a.w);
                H.z = cvt16(b.x, b.y);
                H.w = cvt16(b.z, b.w);
            }
            *(uint4*)(smem + OF_XH + row * 256 + ((c ^ (row & 7)) << 4)) = H;
        }
        __syncthreads();

        // ---- layer 1: warp's [16,128] @ W1^T[128,64], single fp16 product ----
        float acc[8][4];
        #pragma unroll
        for (int nt = 0; nt < 8; ++nt)
            #pragma unroll
            for (int j = 0; j < 4; ++j) acc[nt][j] = 0.f;

        #pragma unroll 1
        for (int ks = 0; ks < 8; ++ks) {
            const int cc = ks * 2 + (L >> 4);
            uint32_t ah[4], bw[4][4];
            {
                int r = m0 + (L & 15);
                ldsm4(ah, sb + OF_XH + r * 256 + ((cc ^ (r & 7)) << 4));
            }
            #pragma unroll
            for (int np = 0; np < 4; ++np) {
                int rn = np * 16 + (L & 15);
                ldsm4(bw[np], sb + OF_W1 + rn * 256 + ((cc ^ (rn & 7)) << 4));
            }
            #pragma unroll
            for (int np = 0; np < 4; ++np) {
                hmma(acc[2 * np],     ah, bw[np][0], bw[np][2]);
                hmma(acc[2 * np + 1], ah, bw[np][1], bw[np][3]);
            }
        }

        // ---- epilogue 1: relu(acc+b1) -> layer-2 A fragments (fp16, registers) ----
        uint32_t a2h[4][4];
        #pragma unroll
        for (int kt = 0; kt < 4; ++kt)
            #pragma unroll
            for (int hf = 0; hf < 2; ++hf) {
                const int nt = 2 * kt + hf;
                const float* d = acc[nt];
                const int c0 = nt * 8 + (L & 3) * 2;
                float2 bb = *(float2*)(b1s + c0);
                float h0 = fmaxf(d[0] + bb.x, 0.f), h1 = fmaxf(d[1] + bb.y, 0.f);
                float h2 = fmaxf(d[2] + bb.x, 0.f), h3 = fmaxf(d[3] + bb.y, 0.f);
                a2h[kt][2 * hf]     = cvt16(h0, h1);
                a2h[kt][2 * hf + 1] = cvt16(h2, h3);
            }

        // ---- layer 2 + gate + scatter, 4 chunks of (32 gate + 32 value) cols ----
        const int gi1 = sGI[m0 + (L >> 2)];
        const int gi2 = sGI[m0 + (L >> 2) + 8];
        float* const gs1p = g_graph_states + (size_t)(gi1 < 0 ? 0 : gi1) * GS;
        float* const gs2p = g_graph_states + (size_t)(gi2 < 0 ? 0 : gi2) * GS;

        #pragma unroll 1
        for (int ch = 0; ch < 4; ++ch) {
            float aG[4][4], aV[4][4];
            #pragma unroll
            for (int nt = 0; nt < 4; ++nt)
                #pragma unroll
                for (int j = 0; j < 4; ++j) { aG[nt][j] = 0.f; aV[nt][j] = 0.f; }

            #pragma unroll
            for (int ks = 0; ks < 4; ++ks) {
                const int cc = ks * 2 + (L >> 4);
                uint32_t bg[2][4], bv[2][4];
                #pragma unroll
                for (int np = 0; np < 2; ++np) {
                    int rg = 32 * ch + np * 16 + (L & 15);
                    int rv = 128 + 32 * ch + np * 16 + (L & 15);
                    ldsm4(bg[np], sb + OF_W2 + rg * 128 + ((cc ^ (rg & 7)) << 4));
                    ldsm4(bv[np], sb + OF_W2 + rv * 128 + ((cc ^ (rv & 7)) << 4));
                }
                #pragma unroll
                for (int np = 0; np < 2; ++np) {
                    hmma(aG[2 * np],     a2h[ks], bg[np][0], bg[np][2]);
                    hmma(aG[2 * np + 1], a2h[ks], bg[np][1], bg[np][3]);
                    hmma(aV[2 * np],     a2h[ks], bv[np][0], bv[np][2]);
                    hmma(aV[2 * np + 1], a2h[ks], bv[np][1], bv[np][3]);
                }
            }

            // ---- epilogue: gated = v*sigmoid(g) -> red.v2 (plain) ----
            #pragma unroll
            for (int nt = 0; nt < 4; ++nt) {
                const int cg = 32 * ch + nt * 8 + (L & 3) * 2;
                float2 bgc = *(float2*)(b2s + cg);
                float2 bvc = *(float2*)(b2s + 128 + cg);
                float gr0 = sigmul(aV[nt][0] + bvc.x, aG[nt][0] + bgc.x);
                float gr1 = sigmul(aV[nt][1] + bvc.y, aG[nt][1] + bgc.y);
                float gs0 = sigmul(aV[nt][2] + bvc.x, aG[nt][2] + bgc.x);
                float gs1 = sigmul(aV[nt][3] + bvc.y, aG[nt][3] + bgc.y);
                if (gi1 >= 0) red2(gs1p + cg, gr0, gr1);
                if (gi2 >= 0) red2(gs2p + cg, gs0, gs1);
            }
        }
        __syncthreads();   // all reads of XH/sGI done before next tile's staging
    }
}

// ---------------- MLP2 + re-zero accumulator ----------------
__global__ __launch_bounds__(128) void mlp2_rezero_kernel(
    const float* __restrict__ W3, const float* __restrict__ b3,
    const float* __restrict__ W4, const float* __restrict__ b4,
    float* __restrict__ out)
{
    __shared__ float W3s[GS * 32];
    __shared__ float W4s[32 * 16];
    __shared__ float b3s[32];
    __shared__ float b4s[16];

    const int tid = threadIdx.x;
    for (int i = tid; i < (GS * 32) / 4; i += 128) ((float4*)W3s)[i] = ((const float4*)W3)[i];
    for (int i = tid; i < (32 * 16) / 4; i += 128) ((float4*)W4s)[i] = ((const float4*)W4)[i];
    if (tid < 32) b3s[tid] = b3[tid];
    if (tid < 16) b4s[tid] = b4[tid];
    __syncthreads();

    const int g = blockIdx.x * 128 + tid;

    float h3[32];
    #pragma unroll
    for (int j = 0; j < 32; ++j) h3[j] = b3s[j];

    float4* gr = (float4*)(g_graph_states + (size_t)g * GS);
    #pragma unroll 1
    for (int k4 = 0; k4 < GS / 4; ++k4) {
        const float4 gv = gr[k4];
        #pragma unroll
        for (int kk = 0; kk < 4; ++kk) {
            const float gk = (kk == 0) ? gv.x : (kk == 1) ? gv.y : (kk == 2) ? gv.z : gv.w;
            const float* w = &W3s[(k4 * 4 + kk) * 32];
            #pragma unroll
            for (int j = 0; j < 32; ++j) h3[j] += gk * w[j];
        }
    }
    #pragma unroll
    for (int k4 = 0; k4 < GS / 4; ++k4) gr[k4] = make_float4(0.f, 0.f, 0.f, 0.f);

    float o[16];
    #pragma unroll
    for (int j = 0; j < 16; ++j) o[j] = b4s[j];
    #pragma unroll
    for (int k = 0; k < 32; ++k) {
        const float hk = fmaxf(h3[k], 0.f);
        #pragma unroll
        for (int j = 0; j < 16; ++j) o[j] += hk * W4s[k * 16 + j];
    }

    float4* op = (float4*)(out + (size_t)g * 16);
    op[0] = make_float4(o[0],  o[1],  o[2],  o[3]);
    op[1] = make_float4(o[4],  o[5],  o[6],  o[7]);
    op[2] = make_float4(o[8],  o[9],  o[10], o[11]);
    op[3] = make_float4(o[12], o[13], o[14], o[15]);
}

extern "C" void kernel_launch(void* const* d_in, const int* in_sizes, int n_in,
                              void* d_out, int out_size)
{
    const float* X  = (const float*)d_in[0];
    const int*   gi = (const int*)  d_in[1];
    const float* W1 = (const float*)d_in[2];
    const float* b1 = (const float*)d_in[3];
    const float* W2 = (const float*)d_in[4];
    const float* b2 = (const float*)d_in[5];
    const float* W3 = (const float*)d_in[6];
    const float* b3 = (const float*)d_in[7];
    const float* W4 = (const float*)d_in[8];
    const float* b4 = (const float*)d_in[9];
    float* out = (float*)d_out;

    cudaFuncSetAttribute(mma_fused_kernel,
                         cudaFuncAttributeMaxDynamicSharedMemorySize, SMEM_TOTAL);

    prep_kernel<<<64, 256>>>(W1, W2);
    // 4 no-ops so ncu's "-s 5" capture lands on mma_fused_kernel (launch #5)
    dummy_kernel<<<1, 32>>>();
    dummy_kernel<<<1, 32>>>();
    dummy_kernel<<<1, 32>>>();
    dummy_kernel<<<1, 32>>>();
    // g_graph_states: zero-initialized at load; re-zeroed by mlp2_rezero each call.
    mma_fused_kernel<<<296, 256, SMEM_TOTAL>>>(X, gi, b1, b2, 0, N_TILES);
    mlp2_rezero_kernel<<<NG / 128, 128>>>(W3, b3, W4, b4, out);
}